// round 1
// baseline (speedup 1.0000x reference)
#include <cuda_runtime.h>
#include <cstdint>

#define MTOK 4096      // B*S
#define DMODEL 2048
#define NHEAD 16
#define DHEAD 128
#define BATCH 2
#define SEQ 2048

// ---- scratch (no cudaMalloc allowed) ----
__device__ float g_q[MTOK * DMODEL];
__device__ float g_k[MTOK * DMODEL];
__device__ float g_v[MTOK * DMODEL];
__device__ float g_o[MTOK * DMODEL];   // [B,H,S,DH] contiguous == buggy [B,S,D] flat view
__device__ float g_h1[MTOK * DMODEL];
__device__ float g_h2[MTOK * DMODEL];

// ============================================================
// GEMM: C[M,N] = A[M,K] @ W[K,N] + bias[N]   (fp32, 128x128x8)
// ============================================================
#define GBM 128
#define GBN 128
#define GBK 8

__global__ void __launch_bounds__(256, 2) gemm_bias_kernel(
    const float* __restrict__ A, const float* __restrict__ W,
    const float* __restrict__ bias, float* __restrict__ C,
    int M, int N, int K)
{
    __shared__ float As[2][GBK][GBM];   // transposed A tile
    __shared__ float Ws[2][GBK][GBN];

    const int tid = threadIdx.x;
    const int tr = tid >> 4;            // 0..15
    const int tc = tid & 15;            // 0..15
    const int rowBase = blockIdx.y * GBM;
    const int colBase = blockIdx.x * GBN;

    const int a_row = tid >> 1;         // 0..127
    const int a_col = (tid & 1) * 4;    // 0 or 4
    const int w_row = tid >> 5;         // 0..7
    const int w_col = (tid & 31) * 4;   // 0..124

    const float* Ag = A + (size_t)(rowBase + a_row) * K + a_col;
    const float* Wg = W + (size_t)w_row * N + colBase + w_col;

    float acc[8][8];
    #pragma unroll
    for (int i = 0; i < 8; i++)
        #pragma unroll
        for (int j = 0; j < 8; j++) acc[i][j] = 0.f;

    // prologue: tile 0
    float4 ra = *(const float4*)(Ag);
    float4 rw = *(const float4*)(Wg);
    As[0][a_col + 0][a_row] = ra.x;
    As[0][a_col + 1][a_row] = ra.y;
    As[0][a_col + 2][a_row] = ra.z;
    As[0][a_col + 3][a_row] = ra.w;
    *(float4*)&Ws[0][w_row][w_col] = rw;
    __syncthreads();

    int buf = 0;
    for (int k0 = 0; k0 < K; k0 += GBK) {
        const bool pf = (k0 + GBK) < K;
        if (pf) {
            ra = *(const float4*)(Ag + k0 + GBK);
            rw = *(const float4*)(Wg + (size_t)(k0 + GBK) * N);
        }
        #pragma unroll
        for (int kk = 0; kk < GBK; kk++) {
            float4 a0 = *(float4*)&As[buf][kk][tr * 4];
            float4 a1 = *(float4*)&As[buf][kk][64 + tr * 4];
            float4 w0 = *(float4*)&Ws[buf][kk][tc * 4];
            float4 w1 = *(float4*)&Ws[buf][kk][64 + tc * 4];
            float ar[8] = {a0.x, a0.y, a0.z, a0.w, a1.x, a1.y, a1.z, a1.w};
            float wr[8] = {w0.x, w0.y, w0.z, w0.w, w1.x, w1.y, w1.z, w1.w};
            #pragma unroll
            for (int i = 0; i < 8; i++)
                #pragma unroll
                for (int j = 0; j < 8; j++)
                    acc[i][j] += ar[i] * wr[j];
        }
        if (pf) {
            int nb = buf ^ 1;
            As[nb][a_col + 0][a_row] = ra.x;
            As[nb][a_col + 1][a_row] = ra.y;
            As[nb][a_col + 2][a_row] = ra.z;
            As[nb][a_col + 3][a_row] = ra.w;
            *(float4*)&Ws[nb][w_row][w_col] = rw;
        }
        __syncthreads();
        buf ^= 1;
    }

    float4 b0 = *(const float4*)&bias[colBase + tc * 4];
    float4 b1 = *(const float4*)&bias[colBase + 64 + tc * 4];
    #pragma unroll
    for (int i = 0; i < 8; i++) {
        int r = rowBase + ((i < 4) ? (tr * 4 + i) : (64 + tr * 4 + (i - 4)));
        float* Cp = C + (size_t)r * N + colBase;
        float4 o0 = make_float4(acc[i][0] + b0.x, acc[i][1] + b0.y,
                                acc[i][2] + b0.z, acc[i][3] + b0.w);
        float4 o1 = make_float4(acc[i][4] + b1.x, acc[i][5] + b1.y,
                                acc[i][6] + b1.z, acc[i][7] + b1.w);
        *(float4*)(Cp + tc * 4) = o0;
        *(float4*)(Cp + 64 + tc * 4) = o1;
    }
}

// ============================================================
// Flash attention: per (b,h,qtile) block; BQ=BKV=64, DH=128
// Q/K/V read as [B,S,D] slices (row stride D); O written [B,H,S,DH] contig.
// ============================================================
#define BQ 64
#define BKV 64
#define QKV_STRIDE 132   // 128 + 4 pad
#define P_STRIDE 68      // 64 + 4 pad

extern __shared__ float fa_smem[];

__global__ void __launch_bounds__(256, 2) flash_attn_kernel(
    const float* __restrict__ Q, const float* __restrict__ K,
    const float* __restrict__ V, float* __restrict__ O)
{
    float* Qs  = fa_smem;                       // [64][132]
    float* KPs = fa_smem + 64 * QKV_STRIDE;     // K tile, recycled as P [64][68]
    float* Vs  = KPs + 64 * QKV_STRIDE;         // [64][132]

    const int tid = threadIdx.x;
    const int tr = tid >> 4;     // 0..15 -> rows 4*tr..4*tr+3
    const int tc = tid & 15;     // 0..15
    const int q0 = blockIdx.x * BQ;
    const int h  = blockIdx.y;
    const int b  = blockIdx.z;
    const float scale = 0.088388347648318447f;  // 1/sqrt(128)

    const size_t base = (size_t)b * SEQ * DMODEL + (size_t)h * DHEAD;

    // load Q tile
    for (int f = tid; f < 64 * 32; f += 256) {
        int r = f >> 5, c4 = (f & 31) << 2;
        *(float4*)&Qs[r * QKV_STRIDE + c4] =
            *(const float4*)(Q + base + (size_t)(q0 + r) * DMODEL + c4);
    }

    float m_i[4], l_i[4], o_acc[4][8];
    #pragma unroll
    for (int i = 0; i < 4; i++) {
        m_i[i] = -3.4028234e38f;
        l_i[i] = 0.f;
        #pragma unroll
        for (int j = 0; j < 8; j++) o_acc[i][j] = 0.f;
    }

    for (int t0 = 0; t0 < SEQ; t0 += BKV) {
        __syncthreads();   // previous iter's P/V reads done
        for (int f = tid; f < 64 * 32; f += 256) {
            int r = f >> 5, c4 = (f & 31) << 2;
            *(float4*)&KPs[r * QKV_STRIDE + c4] =
                *(const float4*)(K + base + (size_t)(t0 + r) * DMODEL + c4);
            *(float4*)&Vs[r * QKV_STRIDE + c4] =
                *(const float4*)(V + base + (size_t)(t0 + r) * DMODEL + c4);
        }
        __syncthreads();

        // S = Q K^T * scale ; thread owns rows {4tr+i}, cols {16j+tc}
        float s[4][4];
        #pragma unroll
        for (int i = 0; i < 4; i++)
            #pragma unroll
            for (int j = 0; j < 4; j++) s[i][j] = 0.f;

        for (int d4 = 0; d4 < 32; d4++) {
            float4 qv[4], kv[4];
            #pragma unroll
            for (int i = 0; i < 4; i++)
                qv[i] = *(float4*)&Qs[(4 * tr + i) * QKV_STRIDE + d4 * 4];
            #pragma unroll
            for (int j = 0; j < 4; j++)
                kv[j] = *(float4*)&KPs[(16 * j + tc) * QKV_STRIDE + d4 * 4];
            #pragma unroll
            for (int i = 0; i < 4; i++)
                #pragma unroll
                for (int j = 0; j < 4; j++) {
                    s[i][j] += qv[i].x * kv[j].x;
                    s[i][j] += qv[i].y * kv[j].y;
                    s[i][j] += qv[i].z * kv[j].z;
                    s[i][j] += qv[i].w * kv[j].w;
                }
        }

        // online softmax update (reduce over 16 tc lanes = half-warp)
        #pragma unroll
        for (int i = 0; i < 4; i++) {
            float mt = s[i][0] * scale;
            #pragma unroll
            for (int j = 1; j < 4; j++) mt = fmaxf(mt, s[i][j] * scale);
            #pragma unroll
            for (int off = 8; off >= 1; off >>= 1)
                mt = fmaxf(mt, __shfl_xor_sync(0xffffffffu, mt, off));
            float mnew = fmaxf(m_i[i], mt);
            float corr = __expf(m_i[i] - mnew);
            float rs = 0.f;
            #pragma unroll
            for (int j = 0; j < 4; j++) {
                s[i][j] = __expf(s[i][j] * scale - mnew);
                rs += s[i][j];
            }
            #pragma unroll
            for (int off = 8; off >= 1; off >>= 1)
                rs += __shfl_xor_sync(0xffffffffu, rs, off);
            l_i[i] = l_i[i] * corr + rs;
            m_i[i] = mnew;
            #pragma unroll
            for (int jj = 0; jj < 8; jj++) o_acc[i][jj] *= corr;
        }
        __syncthreads();   // done reading K tile

        // stage P into recycled K buffer
        #pragma unroll
        for (int i = 0; i < 4; i++)
            #pragma unroll
            for (int j = 0; j < 4; j++)
                KPs[(4 * tr + i) * P_STRIDE + 16 * j + tc] = s[i][j];
        __syncthreads();

        // O += P @ V ; thread cols {tc*4+j, 64+tc*4+j}
        for (int kk = 0; kk < BKV; kk++) {
            float p[4];
            #pragma unroll
            for (int i = 0; i < 4; i++) p[i] = KPs[(4 * tr + i) * P_STRIDE + kk];
            float4 v0 = *(float4*)&Vs[kk * QKV_STRIDE + tc * 4];
            float4 v1 = *(float4*)&Vs[kk * QKV_STRIDE + 64 + tc * 4];
            #pragma unroll
            for (int i = 0; i < 4; i++) {
                o_acc[i][0] += p[i] * v0.x;
                o_acc[i][1] += p[i] * v0.y;
                o_acc[i][2] += p[i] * v0.z;
                o_acc[i][3] += p[i] * v0.w;
                o_acc[i][4] += p[i] * v1.x;
                o_acc[i][5] += p[i] * v1.y;
                o_acc[i][6] += p[i] * v1.z;
                o_acc[i][7] += p[i] * v1.w;
            }
        }
    }

    // epilogue: normalize and write [B,H,S,DH] contiguous
    #pragma unroll
    for (int i = 0; i < 4; i++) {
        float inv = 1.f / l_i[i];
        size_t ob = (((size_t)b * NHEAD + h) * SEQ + (q0 + 4 * tr + i)) * DHEAD;
        float4 o0 = make_float4(o_acc[i][0] * inv, o_acc[i][1] * inv,
                                o_acc[i][2] * inv, o_acc[i][3] * inv);
        float4 o1 = make_float4(o_acc[i][4] * inv, o_acc[i][5] * inv,
                                o_acc[i][6] * inv, o_acc[i][7] * inv);
        *(float4*)(O + ob + tc * 4) = o0;
        *(float4*)(O + ob + 64 + tc * 4) = o1;
    }
}

// ============================================================
// out = LayerNorm(A + Bb) * gamma + beta   (row = 2048)
// ============================================================
__global__ void __launch_bounds__(256) add_ln_kernel(
    const float* __restrict__ A, const float* __restrict__ Bb,
    const float* __restrict__ gamma, const float* __restrict__ beta,
    float* __restrict__ out)
{
    const int row = blockIdx.x;
    const int tid = threadIdx.x;
    const float* a  = A  + (size_t)row * DMODEL;
    const float* bb = Bb + (size_t)row * DMODEL;

    float v[8];
    float s = 0.f, sq = 0.f;
    #pragma unroll
    for (int i = 0; i < 8; i++) {
        int idx = tid + i * 256;
        float x = a[idx] + bb[idx];
        v[i] = x;
        s += x;
        sq += x * x;
    }
    #pragma unroll
    for (int off = 16; off >= 1; off >>= 1) {
        s  += __shfl_xor_sync(0xffffffffu, s, off);
        sq += __shfl_xor_sync(0xffffffffu, sq, off);
    }
    __shared__ float red[2][8];
    __shared__ float fmean, finv;
    int wid = tid >> 5, lane = tid & 31;
    if (lane == 0) { red[0][wid] = s; red[1][wid] = sq; }
    __syncthreads();
    if (tid == 0) {
        float ts = 0.f, tq = 0.f;
        #pragma unroll
        for (int w = 0; w < 8; w++) { ts += red[0][w]; tq += red[1][w]; }
        float mean = ts * (1.f / DMODEL);
        float var = tq * (1.f / DMODEL) - mean * mean;
        fmean = mean;
        finv = rsqrtf(var + 1e-5f);
    }
    __syncthreads();
    float mean = fmean, inv = finv;
    float* op = out + (size_t)row * DMODEL;
    #pragma unroll
    for (int i = 0; i < 8; i++) {
        int idx = tid + i * 256;
        op[idx] = (v[i] - mean) * inv * gamma[idx] + beta[idx];
    }
}

// ============================================================
extern "C" void kernel_launch(void* const* d_in, const int* in_sizes, int n_in,
                              void* d_out, int out_size)
{
    const float* x     = (const float*)d_in[0];
    const float* wq    = (const float*)d_in[1];
    const float* bq    = (const float*)d_in[2];
    const float* wk    = (const float*)d_in[3];
    const float* bk    = (const float*)d_in[4];
    const float* wv    = (const float*)d_in[5];
    const float* bv    = (const float*)d_in[6];
    const float* wf    = (const float*)d_in[7];
    const float* bf    = (const float*)d_in[8];
    const float* gamma = (const float*)d_in[9];
    const float* beta  = (const float*)d_in[10];
    float* out = (float*)d_out;

    float *q, *k, *v, *o, *h1, *h2;
    cudaGetSymbolAddress((void**)&q,  g_q);
    cudaGetSymbolAddress((void**)&k,  g_k);
    cudaGetSymbolAddress((void**)&v,  g_v);
    cudaGetSymbolAddress((void**)&o,  g_o);
    cudaGetSymbolAddress((void**)&h1, g_h1);
    cudaGetSymbolAddress((void**)&h2, g_h2);

    const dim3 gemm_grid(DMODEL / GBN, MTOK / GBM);  // (16, 32)

    gemm_bias_kernel<<<gemm_grid, 256>>>(x, wq, bq, q, MTOK, DMODEL, DMODEL);
    gemm_bias_kernel<<<gemm_grid, 256>>>(x, wk, bk, k, MTOK, DMODEL, DMODEL);
    gemm_bias_kernel<<<gemm_grid, 256>>>(x, wv, bv, v, MTOK, DMODEL, DMODEL);

    size_t fa_bytes = (size_t)3 * 64 * QKV_STRIDE * sizeof(float);  // 101376
    cudaFuncSetAttribute(flash_attn_kernel,
                         cudaFuncAttributeMaxDynamicSharedMemorySize,
                         (int)fa_bytes);
    flash_attn_kernel<<<dim3(SEQ / BQ, NHEAD, BATCH), 256, fa_bytes>>>(q, k, v, o);

    add_ln_kernel<<<MTOK, 256>>>(o, x, gamma, beta, h1);
    gemm_bias_kernel<<<gemm_grid, 256>>>(h1, wf, bf, h2, MTOK, DMODEL, DMODEL);
    add_ln_kernel<<<MTOK, 256>>>(h2, o, gamma, beta, out);
}

// round 2
// speedup vs baseline: 2.4306x; 2.4306x over previous
#include <cuda_runtime.h>
#include <cstdint>

#define MTOK 4096      // B*S
#define DMODEL 2048
#define NHEAD 16
#define DHEAD 128
#define BATCH 2
#define SEQ 2048

// ---- scratch (no cudaMalloc allowed) ----
__device__ float g_q[MTOK * DMODEL];
__device__ float g_k[MTOK * DMODEL];
__device__ float g_v[MTOK * DMODEL];
__device__ float g_o[MTOK * DMODEL];   // [B,H,S,DH] contiguous == buggy [B,S,D] flat view
__device__ float g_h1[MTOK * DMODEL];
__device__ float g_h2[MTOK * DMODEL];

// ============================================================
// TF32 tensor-core GEMM: C[M,N] = A[M,K] @ W[K,N] + bias[N]
// block tile 128x128x32, 8 warps (64x32 warp tiles), 2-stage cp.async
// ============================================================
#define TBM 128
#define TBN 128
#define TBK 32
#define AS_STRIDE 36            // 128+... row-major [row][k], 144B rows (16B aligned, conflict-free frags)
#define BS_STRIDE 136           // [k][n], 544B rows (16B aligned; 136%32==8 -> conflict-free frags)
#define AS_SIZE (TBM * AS_STRIDE)      // 4608 floats
#define BS_SIZE (TBK * BS_STRIDE)      // 4352 floats
#define STAGE_SIZE (AS_SIZE + BS_SIZE) // 8960 floats = 35840 B

__device__ __forceinline__ void cp_async16(uint32_t saddr, const void* gaddr) {
    asm volatile("cp.async.cg.shared.global [%0], [%1], 16;\n" :: "r"(saddr), "l"(gaddr));
}
__device__ __forceinline__ void cp_commit() {
    asm volatile("cp.async.commit_group;\n");
}
__device__ __forceinline__ uint32_t f2tf32(float x) {
    uint32_t r;
    asm("cvt.rna.tf32.f32 %0, %1;" : "=r"(r) : "f"(x));
    return r;
}
__device__ __forceinline__ void mma_tf32(float* c, const uint32_t* a, const uint32_t* b) {
    asm volatile(
        "mma.sync.aligned.m16n8k8.row.col.f32.tf32.tf32.f32 "
        "{%0,%1,%2,%3}, {%4,%5,%6,%7}, {%8,%9}, {%0,%1,%2,%3};\n"
        : "+f"(c[0]), "+f"(c[1]), "+f"(c[2]), "+f"(c[3])
        : "r"(a[0]), "r"(a[1]), "r"(a[2]), "r"(a[3]), "r"(b[0]), "r"(b[1]));
}

extern __shared__ float g_smem[];

__global__ void __launch_bounds__(256, 2) gemm_tf32_kernel(
    const float* __restrict__ A, const float* __restrict__ W,
    const float* __restrict__ bias, float* __restrict__ C,
    int M, int N, int K)
{
    const int tid = threadIdx.x;
    const int wid = tid >> 5;
    const int lane = tid & 31;
    const int g = lane >> 2;        // group id 0..7
    const int t = lane & 3;         // thread-in-group 0..3
    const int wr = wid >> 2;        // 0..1 -> warp row (64 rows each)
    const int wc = wid & 3;         // 0..3 -> warp col (32 cols each)
    const int R = wr * 64;
    const int Cc = wc * 32;
    const int rowBase = blockIdx.y * TBM;
    const int colBase = blockIdx.x * TBN;

    float* stage[2] = { g_smem, g_smem + STAGE_SIZE };

    // per-thread load decomposition (A: 1024 f4 chunks, B: 1024 f4 chunks)
    const int a_r  = (tid * 4 + 0) >> 5;                 // unused form; real below
    (void)a_r;

    auto load_stage = [&](int s, int k0) {
        float* as = stage[s];
        float* bs = stage[s] + AS_SIZE;
        uint32_t as_u = (uint32_t)__cvta_generic_to_shared(as);
        uint32_t bs_u = (uint32_t)__cvta_generic_to_shared(bs);
        #pragma unroll
        for (int i = 0; i < 4; i++) {
            int c = tid + i * 256;          // 0..1023
            int r  = c >> 3;                // 0..127
            int k4 = (c & 7) * 4;           // 0..28
            cp_async16(as_u + (uint32_t)(r * AS_STRIDE + k4) * 4,
                       A + (size_t)(rowBase + r) * K + k0 + k4);
        }
        #pragma unroll
        for (int i = 0; i < 4; i++) {
            int c = tid + i * 256;
            int r  = c >> 5;                // 0..31
            int n4 = (c & 31) * 4;          // 0..124
            cp_async16(bs_u + (uint32_t)(r * BS_STRIDE + n4) * 4,
                       W + (size_t)(k0 + r) * N + colBase + n4);
        }
        cp_commit();
    };

    float acc[4][4][4];
    #pragma unroll
    for (int mi = 0; mi < 4; mi++)
        #pragma unroll
        for (int ni = 0; ni < 4; ni++)
            #pragma unroll
            for (int r = 0; r < 4; r++) acc[mi][ni][r] = 0.f;

    const int T = K / TBK;      // 64
    load_stage(0, 0);

    int buf = 0;
    for (int it = 0; it < T; it++) {
        if (it + 1 < T) {
            load_stage(buf ^ 1, (it + 1) * TBK);
            asm volatile("cp.async.wait_group 1;\n");
        } else {
            asm volatile("cp.async.wait_group 0;\n");
        }
        __syncthreads();

        const float* as = stage[buf];
        const float* bs = stage[buf] + AS_SIZE;

        #pragma unroll
        for (int ks = 0; ks < 4; ks++) {
            const int kk = ks * 8;
            uint32_t af[4][4], bf[4][2];
            #pragma unroll
            for (int mi = 0; mi < 4; mi++) {
                int r0 = R + mi * 16 + g;
                af[mi][0] = f2tf32(as[r0 * AS_STRIDE + kk + t]);
                af[mi][1] = f2tf32(as[(r0 + 8) * AS_STRIDE + kk + t]);
                af[mi][2] = f2tf32(as[r0 * AS_STRIDE + kk + t + 4]);
                af[mi][3] = f2tf32(as[(r0 + 8) * AS_STRIDE + kk + t + 4]);
            }
            #pragma unroll
            for (int ni = 0; ni < 4; ni++) {
                int c0 = Cc + ni * 8 + g;
                bf[ni][0] = f2tf32(bs[(kk + t) * BS_STRIDE + c0]);
                bf[ni][1] = f2tf32(bs[(kk + t + 4) * BS_STRIDE + c0]);
            }
            #pragma unroll
            for (int mi = 0; mi < 4; mi++)
                #pragma unroll
                for (int ni = 0; ni < 4; ni++)
                    mma_tf32(acc[mi][ni], af[mi], bf[ni]);
        }
        __syncthreads();
        buf ^= 1;
    }

    // epilogue: bias + store (c0,c1 contiguous -> float2; c2,c3 row+8)
    #pragma unroll
    for (int mi = 0; mi < 4; mi++) {
        int r0 = rowBase + R + mi * 16 + g;
        #pragma unroll
        for (int ni = 0; ni < 4; ni++) {
            int cb = colBase + Cc + ni * 8 + 2 * t;
            float bx = bias[cb], by = bias[cb + 1];
            float2 v0 = make_float2(acc[mi][ni][0] + bx, acc[mi][ni][1] + by);
            float2 v1 = make_float2(acc[mi][ni][2] + bx, acc[mi][ni][3] + by);
            *(float2*)(C + (size_t)r0 * N + cb) = v0;
            *(float2*)(C + (size_t)(r0 + 8) * N + cb) = v1;
        }
    }
}

// ============================================================
// Flash attention: per (b,h,qtile) block; BQ=BKV=64, DH=128 (fp32)
// ============================================================
#define BQ 64
#define BKV 64
#define QKV_STRIDE 132   // 128 + 4 pad
#define P_STRIDE 68      // 64 + 4 pad

__global__ void __launch_bounds__(256, 2) flash_attn_kernel(
    const float* __restrict__ Q, const float* __restrict__ K,
    const float* __restrict__ V, float* __restrict__ O)
{
    float* Qs  = g_smem;                        // [64][132]
    float* KPs = g_smem + 64 * QKV_STRIDE;      // K tile, recycled as P [64][68]
    float* Vs  = KPs + 64 * QKV_STRIDE;         // [64][132]

    const int tid = threadIdx.x;
    const int tr = tid >> 4;     // 0..15 -> rows 4*tr..4*tr+3
    const int tc = tid & 15;     // 0..15
    const int q0 = blockIdx.x * BQ;
    const int h  = blockIdx.y;
    const int b  = blockIdx.z;
    const float scale = 0.088388347648318447f;  // 1/sqrt(128)

    const size_t base = (size_t)b * SEQ * DMODEL + (size_t)h * DHEAD;

    for (int f = tid; f < 64 * 32; f += 256) {
        int r = f >> 5, c4 = (f & 31) << 2;
        *(float4*)&Qs[r * QKV_STRIDE + c4] =
            *(const float4*)(Q + base + (size_t)(q0 + r) * DMODEL + c4);
    }

    float m_i[4], l_i[4], o_acc[4][8];
    #pragma unroll
    for (int i = 0; i < 4; i++) {
        m_i[i] = -3.4028234e38f;
        l_i[i] = 0.f;
        #pragma unroll
        for (int j = 0; j < 8; j++) o_acc[i][j] = 0.f;
    }

    for (int t0 = 0; t0 < SEQ; t0 += BKV) {
        __syncthreads();
        for (int f = tid; f < 64 * 32; f += 256) {
            int r = f >> 5, c4 = (f & 31) << 2;
            *(float4*)&KPs[r * QKV_STRIDE + c4] =
                *(const float4*)(K + base + (size_t)(t0 + r) * DMODEL + c4);
            *(float4*)&Vs[r * QKV_STRIDE + c4] =
                *(const float4*)(V + base + (size_t)(t0 + r) * DMODEL + c4);
        }
        __syncthreads();

        float s[4][4];
        #pragma unroll
        for (int i = 0; i < 4; i++)
            #pragma unroll
            for (int j = 0; j < 4; j++) s[i][j] = 0.f;

        for (int d4 = 0; d4 < 32; d4++) {
            float4 qv[4], kv[4];
            #pragma unroll
            for (int i = 0; i < 4; i++)
                qv[i] = *(float4*)&Qs[(4 * tr + i) * QKV_STRIDE + d4 * 4];
            #pragma unroll
            for (int j = 0; j < 4; j++)
                kv[j] = *(float4*)&KPs[(16 * j + tc) * QKV_STRIDE + d4 * 4];
            #pragma unroll
            for (int i = 0; i < 4; i++)
                #pragma unroll
                for (int j = 0; j < 4; j++) {
                    s[i][j] += qv[i].x * kv[j].x;
                    s[i][j] += qv[i].y * kv[j].y;
                    s[i][j] += qv[i].z * kv[j].z;
                    s[i][j] += qv[i].w * kv[j].w;
                }
        }

        #pragma unroll
        for (int i = 0; i < 4; i++) {
            float mt = s[i][0] * scale;
            #pragma unroll
            for (int j = 1; j < 4; j++) mt = fmaxf(mt, s[i][j] * scale);
            #pragma unroll
            for (int off = 8; off >= 1; off >>= 1)
                mt = fmaxf(mt, __shfl_xor_sync(0xffffffffu, mt, off));
            float mnew = fmaxf(m_i[i], mt);
            float corr = __expf(m_i[i] - mnew);
            float rs = 0.f;
            #pragma unroll
            for (int j = 0; j < 4; j++) {
                s[i][j] = __expf(s[i][j] * scale - mnew);
                rs += s[i][j];
            }
            #pragma unroll
            for (int off = 8; off >= 1; off >>= 1)
                rs += __shfl_xor_sync(0xffffffffu, rs, off);
            l_i[i] = l_i[i] * corr + rs;
            m_i[i] = mnew;
            #pragma unroll
            for (int jj = 0; jj < 8; jj++) o_acc[i][jj] *= corr;
        }
        __syncthreads();

        #pragma unroll
        for (int i = 0; i < 4; i++)
            #pragma unroll
            for (int j = 0; j < 4; j++)
                KPs[(4 * tr + i) * P_STRIDE + 16 * j + tc] = s[i][j];
        __syncthreads();

        for (int kk = 0; kk < BKV; kk++) {
            float p[4];
            #pragma unroll
            for (int i = 0; i < 4; i++) p[i] = KPs[(4 * tr + i) * P_STRIDE + kk];
            float4 v0 = *(float4*)&Vs[kk * QKV_STRIDE + tc * 4];
            float4 v1 = *(float4*)&Vs[kk * QKV_STRIDE + 64 + tc * 4];
            #pragma unroll
            for (int i = 0; i < 4; i++) {
                o_acc[i][0] += p[i] * v0.x;
                o_acc[i][1] += p[i] * v0.y;
                o_acc[i][2] += p[i] * v0.z;
                o_acc[i][3] += p[i] * v0.w;
                o_acc[i][4] += p[i] * v1.x;
                o_acc[i][5] += p[i] * v1.y;
                o_acc[i][6] += p[i] * v1.z;
                o_acc[i][7] += p[i] * v1.w;
            }
        }
    }

    #pragma unroll
    for (int i = 0; i < 4; i++) {
        float inv = 1.f / l_i[i];
        size_t ob = (((size_t)b * NHEAD + h) * SEQ + (q0 + 4 * tr + i)) * DHEAD;
        float4 o0 = make_float4(o_acc[i][0] * inv, o_acc[i][1] * inv,
                                o_acc[i][2] * inv, o_acc[i][3] * inv);
        float4 o1 = make_float4(o_acc[i][4] * inv, o_acc[i][5] * inv,
                                o_acc[i][6] * inv, o_acc[i][7] * inv);
        *(float4*)(O + ob + tc * 4) = o0;
        *(float4*)(O + ob + 64 + tc * 4) = o1;
    }
}

// ============================================================
// out = LayerNorm(A + Bb) * gamma + beta   (row = 2048)
// ============================================================
__global__ void __launch_bounds__(256) add_ln_kernel(
    const float* __restrict__ A, const float* __restrict__ Bb,
    const float* __restrict__ gamma, const float* __restrict__ beta,
    float* __restrict__ out)
{
    const int row = blockIdx.x;
    const int tid = threadIdx.x;
    const float* a  = A  + (size_t)row * DMODEL;
    const float* bb = Bb + (size_t)row * DMODEL;

    float v[8];
    float s = 0.f, sq = 0.f;
    #pragma unroll
    for (int i = 0; i < 8; i++) {
        int idx = tid + i * 256;
        float x = a[idx] + bb[idx];
        v[i] = x;
        s += x;
        sq += x * x;
    }
    #pragma unroll
    for (int off = 16; off >= 1; off >>= 1) {
        s  += __shfl_xor_sync(0xffffffffu, s, off);
        sq += __shfl_xor_sync(0xffffffffu, sq, off);
    }
    __shared__ float red[2][8];
    __shared__ float fmean, finv;
    int wid = tid >> 5, lane = tid & 31;
    if (lane == 0) { red[0][wid] = s; red[1][wid] = sq; }
    __syncthreads();
    if (tid == 0) {
        float ts = 0.f, tq = 0.f;
        #pragma unroll
        for (int w = 0; w < 8; w++) { ts += red[0][w]; tq += red[1][w]; }
        float mean = ts * (1.f / DMODEL);
        float var = tq * (1.f / DMODEL) - mean * mean;
        fmean = mean;
        finv = rsqrtf(var + 1e-5f);
    }
    __syncthreads();
    float mean = fmean, inv = finv;
    float* op = out + (size_t)row * DMODEL;
    #pragma unroll
    for (int i = 0; i < 8; i++) {
        int idx = tid + i * 256;
        op[idx] = (v[i] - mean) * inv * gamma[idx] + beta[idx];
    }
}

// ============================================================
extern "C" void kernel_launch(void* const* d_in, const int* in_sizes, int n_in,
                              void* d_out, int out_size)
{
    const float* x     = (const float*)d_in[0];
    const float* wq    = (const float*)d_in[1];
    const float* bq    = (const float*)d_in[2];
    const float* wk    = (const float*)d_in[3];
    const float* bk    = (const float*)d_in[4];
    const float* wv    = (const float*)d_in[5];
    const float* bv    = (const float*)d_in[6];
    const float* wf    = (const float*)d_in[7];
    const float* bf    = (const float*)d_in[8];
    const float* gamma = (const float*)d_in[9];
    const float* beta  = (const float*)d_in[10];
    float* out = (float*)d_out;

    float *q, *k, *v, *o, *h1, *h2;
    cudaGetSymbolAddress((void**)&q,  g_q);
    cudaGetSymbolAddress((void**)&k,  g_k);
    cudaGetSymbolAddress((void**)&v,  g_v);
    cudaGetSymbolAddress((void**)&o,  g_o);
    cudaGetSymbolAddress((void**)&h1, g_h1);
    cudaGetSymbolAddress((void**)&h2, g_h2);

    const dim3 gemm_grid(DMODEL / TBN, MTOK / TBM);  // (16, 32)
    const size_t gemm_smem = 2 * STAGE_SIZE * sizeof(float);  // 71680

    static int attr_done = 0;
    if (!attr_done) {
        cudaFuncSetAttribute(gemm_tf32_kernel,
                             cudaFuncAttributeMaxDynamicSharedMemorySize,
                             (int)gemm_smem);
        cudaFuncSetAttribute(flash_attn_kernel,
                             cudaFuncAttributeMaxDynamicSharedMemorySize,
                             (int)((size_t)3 * 64 * QKV_STRIDE * sizeof(float)));
        attr_done = 1;
    }

    gemm_tf32_kernel<<<gemm_grid, 256, gemm_smem>>>(x, wq, bq, q, MTOK, DMODEL, DMODEL);
    gemm_tf32_kernel<<<gemm_grid, 256, gemm_smem>>>(x, wk, bk, k, MTOK, DMODEL, DMODEL);
    gemm_tf32_kernel<<<gemm_grid, 256, gemm_smem>>>(x, wv, bv, v, MTOK, DMODEL, DMODEL);

    size_t fa_bytes = (size_t)3 * 64 * QKV_STRIDE * sizeof(float);  // 101376
    flash_attn_kernel<<<dim3(SEQ / BQ, NHEAD, BATCH), 256, fa_bytes>>>(q, k, v, o);

    add_ln_kernel<<<MTOK, 256>>>(o, x, gamma, beta, h1);
    gemm_tf32_kernel<<<gemm_grid, 256, gemm_smem>>>(h1, wf, bf, h2, MTOK, DMODEL, DMODEL);
    add_ln_kernel<<<MTOK, 256>>>(h2, o, gamma, beta, out);
}

// round 3
// speedup vs baseline: 4.1511x; 1.7078x over previous
#include <cuda_runtime.h>
#include <cstdint>

#define MTOK 4096      // B*S
#define DMODEL 2048
#define NHEAD 16
#define DHEAD 128
#define BATCH 2
#define SEQ 2048

// ---- scratch (no cudaMalloc allowed) ----
__device__ float g_q[MTOK * DMODEL];
__device__ float g_k[MTOK * DMODEL];
__device__ float g_v[MTOK * DMODEL];
__device__ float g_o[MTOK * DMODEL];   // [B,H,S,DH] contiguous == buggy [B,S,D] flat view
__device__ float g_h1[MTOK * DMODEL];
__device__ float g_h2[MTOK * DMODEL];

// ============================================================
// common tensor-core helpers (tf32 m16n8k8)
// ============================================================
__device__ __forceinline__ void cp_async16(uint32_t saddr, const void* gaddr) {
    asm volatile("cp.async.cg.shared.global [%0], [%1], 16;\n" :: "r"(saddr), "l"(gaddr));
}
__device__ __forceinline__ void cp_commit() {
    asm volatile("cp.async.commit_group;\n");
}
__device__ __forceinline__ uint32_t f2tf32(float x) {
    uint32_t r;
    asm("cvt.rna.tf32.f32 %0, %1;" : "=r"(r) : "f"(x));
    return r;
}
__device__ __forceinline__ void mma_tf32(float* c, const uint32_t* a, const uint32_t* b) {
    asm volatile(
        "mma.sync.aligned.m16n8k8.row.col.f32.tf32.tf32.f32 "
        "{%0,%1,%2,%3}, {%4,%5,%6,%7}, {%8,%9}, {%0,%1,%2,%3};\n"
        : "+f"(c[0]), "+f"(c[1]), "+f"(c[2]), "+f"(c[3])
        : "r"(a[0]), "r"(a[1]), "r"(a[2]), "r"(a[3]), "r"(b[0]), "r"(b[1]));
}

extern __shared__ float g_smem[];

// ============================================================
// TF32 tensor-core GEMM: C[M,N] = A[M,K] @ W[K,N] + bias[N]
// block tile 128x128x32, 8 warps (64x32 warp tiles), 2-stage cp.async
// ============================================================
#define TBM 128
#define TBN 128
#define TBK 32
#define AS_STRIDE 36
#define BS_STRIDE 136
#define AS_SIZE (TBM * AS_STRIDE)
#define BS_SIZE (TBK * BS_STRIDE)
#define STAGE_SIZE (AS_SIZE + BS_SIZE)

__global__ void __launch_bounds__(256, 2) gemm_tf32_kernel(
    const float* __restrict__ A, const float* __restrict__ W,
    const float* __restrict__ bias, float* __restrict__ C,
    int M, int N, int K)
{
    const int tid = threadIdx.x;
    const int wid = tid >> 5;
    const int lane = tid & 31;
    const int g = lane >> 2;
    const int t = lane & 3;
    const int wr = wid >> 2;
    const int wc = wid & 3;
    const int R = wr * 64;
    const int Cc = wc * 32;
    const int rowBase = blockIdx.y * TBM;
    const int colBase = blockIdx.x * TBN;

    float* stage[2] = { g_smem, g_smem + STAGE_SIZE };

    auto load_stage = [&](int s, int k0) {
        float* as = stage[s];
        float* bs = stage[s] + AS_SIZE;
        uint32_t as_u = (uint32_t)__cvta_generic_to_shared(as);
        uint32_t bs_u = (uint32_t)__cvta_generic_to_shared(bs);
        #pragma unroll
        for (int i = 0; i < 4; i++) {
            int c = tid + i * 256;
            int r  = c >> 3;
            int k4 = (c & 7) * 4;
            cp_async16(as_u + (uint32_t)(r * AS_STRIDE + k4) * 4,
                       A + (size_t)(rowBase + r) * K + k0 + k4);
        }
        #pragma unroll
        for (int i = 0; i < 4; i++) {
            int c = tid + i * 256;
            int r  = c >> 5;
            int n4 = (c & 31) * 4;
            cp_async16(bs_u + (uint32_t)(r * BS_STRIDE + n4) * 4,
                       W + (size_t)(k0 + r) * N + colBase + n4);
        }
        cp_commit();
    };

    float acc[4][4][4];
    #pragma unroll
    for (int mi = 0; mi < 4; mi++)
        #pragma unroll
        for (int ni = 0; ni < 4; ni++)
            #pragma unroll
            for (int r = 0; r < 4; r++) acc[mi][ni][r] = 0.f;

    const int T = K / TBK;
    load_stage(0, 0);

    int buf = 0;
    for (int it = 0; it < T; it++) {
        if (it + 1 < T) {
            load_stage(buf ^ 1, (it + 1) * TBK);
            asm volatile("cp.async.wait_group 1;\n");
        } else {
            asm volatile("cp.async.wait_group 0;\n");
        }
        __syncthreads();

        const float* as = stage[buf];
        const float* bs = stage[buf] + AS_SIZE;

        #pragma unroll
        for (int ks = 0; ks < 4; ks++) {
            const int kk = ks * 8;
            uint32_t af[4][4], bf[4][2];
            #pragma unroll
            for (int mi = 0; mi < 4; mi++) {
                int r0 = R + mi * 16 + g;
                af[mi][0] = f2tf32(as[r0 * AS_STRIDE + kk + t]);
                af[mi][1] = f2tf32(as[(r0 + 8) * AS_STRIDE + kk + t]);
                af[mi][2] = f2tf32(as[r0 * AS_STRIDE + kk + t + 4]);
                af[mi][3] = f2tf32(as[(r0 + 8) * AS_STRIDE + kk + t + 4]);
            }
            #pragma unroll
            for (int ni = 0; ni < 4; ni++) {
                int c0 = Cc + ni * 8 + g;
                bf[ni][0] = f2tf32(bs[(kk + t) * BS_STRIDE + c0]);
                bf[ni][1] = f2tf32(bs[(kk + t + 4) * BS_STRIDE + c0]);
            }
            #pragma unroll
            for (int mi = 0; mi < 4; mi++)
                #pragma unroll
                for (int ni = 0; ni < 4; ni++)
                    mma_tf32(acc[mi][ni], af[mi], bf[ni]);
        }
        __syncthreads();
        buf ^= 1;
    }

    #pragma unroll
    for (int mi = 0; mi < 4; mi++) {
        int r0 = rowBase + R + mi * 16 + g;
        #pragma unroll
        for (int ni = 0; ni < 4; ni++) {
            int cb = colBase + Cc + ni * 8 + 2 * t;
            float bx = bias[cb], by = bias[cb + 1];
            float2 v0 = make_float2(acc[mi][ni][0] + bx, acc[mi][ni][1] + by);
            float2 v1 = make_float2(acc[mi][ni][2] + bx, acc[mi][ni][3] + by);
            *(float2*)(C + (size_t)r0 * N + cb) = v0;
            *(float2*)(C + (size_t)(r0 + 8) * N + cb) = v1;
        }
    }
}

// ============================================================
// Tensor-core flash attention (tf32): BQ=64, BKV=64, DH=128
// 128 threads = 4 warps, warp w owns rows 16w..16w+15 of the Q tile.
// Q pre-scaled, held as tf32 A-fragments in registers.
// K smem stride 132 (conflict-free), V stride 136, P stride 68.
// ============================================================
#define FKS 132
#define FVS 136
#define FPS 68

__global__ void __launch_bounds__(128) flash_attn_tc_kernel(
    const float* __restrict__ Q, const float* __restrict__ K,
    const float* __restrict__ V, float* __restrict__ O)
{
    uint32_t* Ks = (uint32_t*)g_smem;          // [64][132] tf32 bits
    uint32_t* Vs = Ks + 64 * FKS;              // [64][136]
    uint32_t* Ps = Vs + 64 * FVS;              // [64][68]

    const int tid = threadIdx.x;
    const int w = tid >> 5;
    const int lane = tid & 31;
    const int g = lane >> 2;
    const int t = lane & 3;
    const int q0 = blockIdx.x * 64;
    const int h  = blockIdx.y;
    const int b  = blockIdx.z;
    const float scale = 0.088388347648318447f;  // 1/sqrt(128)
    const size_t base = (size_t)b * SEQ * DMODEL + (size_t)h * DHEAD;

    // Q fragments (row r0 = q0 + 16w + g, + 8), pre-scaled, tf32
    uint32_t qa[16][4];
    {
        const float* Qp0 = Q + base + (size_t)(q0 + w * 16 + g) * DMODEL;
        const float* Qp1 = Qp0 + (size_t)8 * DMODEL;
        #pragma unroll
        for (int kk = 0; kk < 16; kk++) {
            qa[kk][0] = f2tf32(Qp0[kk * 8 + t] * scale);
            qa[kk][1] = f2tf32(Qp1[kk * 8 + t] * scale);
            qa[kk][2] = f2tf32(Qp0[kk * 8 + t + 4] * scale);
            qa[kk][3] = f2tf32(Qp1[kk * 8 + t + 4] * scale);
        }
    }

    float o_acc[16][4];
    #pragma unroll
    for (int ni = 0; ni < 16; ni++)
        #pragma unroll
        for (int r = 0; r < 4; r++) o_acc[ni][r] = 0.f;
    float m0r = -1e30f, m1r = -1e30f, l0r = 0.f, l1r = 0.f;

    for (int t0 = 0; t0 < SEQ; t0 += 64) {
        __syncthreads();
        // stage K,V tiles converted to tf32
        #pragma unroll
        for (int i = 0; i < 16; i++) {
            int f = tid + i * 128;            // 0..2047 float4 chunks
            int r = f >> 5, c4 = (f & 31) * 4;
            const float* kp = K + base + (size_t)(t0 + r) * DMODEL + c4;
            const float* vp = V + base + (size_t)(t0 + r) * DMODEL + c4;
            float4 k4 = *(const float4*)kp;
            float4 v4 = *(const float4*)vp;
            uint32_t* kd = Ks + r * FKS + c4;
            kd[0] = f2tf32(k4.x); kd[1] = f2tf32(k4.y);
            kd[2] = f2tf32(k4.z); kd[3] = f2tf32(k4.w);
            uint32_t* vd = Vs + r * FVS + c4;
            vd[0] = f2tf32(v4.x); vd[1] = f2tf32(v4.y);
            vd[2] = f2tf32(v4.z); vd[3] = f2tf32(v4.w);
        }
        __syncthreads();

        // S = (Q*scale) @ K^T  -> s[8 n-tiles][4]
        float s[8][4];
        #pragma unroll
        for (int ni = 0; ni < 8; ni++)
            #pragma unroll
            for (int r = 0; r < 4; r++) s[ni][r] = 0.f;

        #pragma unroll
        for (int kk = 0; kk < 16; kk++) {
            #pragma unroll
            for (int ni = 0; ni < 8; ni++) {
                uint32_t bfr[2];
                const uint32_t* kr = Ks + (ni * 8 + g) * FKS + kk * 8 + t;
                bfr[0] = kr[0];
                bfr[1] = kr[4];
                mma_tf32(s[ni], qa[kk], bfr);
            }
        }

        // online softmax (rows g and g+8)
        float mt0 = -1e30f, mt1 = -1e30f;
        #pragma unroll
        for (int ni = 0; ni < 8; ni++) {
            mt0 = fmaxf(mt0, fmaxf(s[ni][0], s[ni][1]));
            mt1 = fmaxf(mt1, fmaxf(s[ni][2], s[ni][3]));
        }
        #pragma unroll
        for (int off = 1; off <= 2; off <<= 1) {
            mt0 = fmaxf(mt0, __shfl_xor_sync(0xffffffffu, mt0, off));
            mt1 = fmaxf(mt1, __shfl_xor_sync(0xffffffffu, mt1, off));
        }
        float mn0 = fmaxf(m0r, mt0), mn1 = fmaxf(m1r, mt1);
        float c0 = __expf(m0r - mn0), c1 = __expf(m1r - mn1);
        float rs0 = 0.f, rs1 = 0.f;
        #pragma unroll
        for (int ni = 0; ni < 8; ni++) {
            s[ni][0] = __expf(s[ni][0] - mn0);
            s[ni][1] = __expf(s[ni][1] - mn0);
            s[ni][2] = __expf(s[ni][2] - mn1);
            s[ni][3] = __expf(s[ni][3] - mn1);
            rs0 += s[ni][0] + s[ni][1];
            rs1 += s[ni][2] + s[ni][3];
        }
        #pragma unroll
        for (int off = 1; off <= 2; off <<= 1) {
            rs0 += __shfl_xor_sync(0xffffffffu, rs0, off);
            rs1 += __shfl_xor_sync(0xffffffffu, rs1, off);
        }
        l0r = l0r * c0 + rs0;  m0r = mn0;
        l1r = l1r * c1 + rs1;  m1r = mn1;
        #pragma unroll
        for (int ni = 0; ni < 16; ni++) {
            o_acc[ni][0] *= c0; o_acc[ni][1] *= c0;
            o_acc[ni][2] *= c1; o_acc[ni][3] *= c1;
        }

        // stage P (tf32) into per-warp smem region
        {
            uint32_t* p0 = Ps + (w * 16 + g) * FPS;
            uint32_t* p1 = Ps + (w * 16 + 8 + g) * FPS;
            #pragma unroll
            for (int ni = 0; ni < 8; ni++) {
                p0[ni * 8 + 2 * t]     = f2tf32(s[ni][0]);
                p0[ni * 8 + 2 * t + 1] = f2tf32(s[ni][1]);
                p1[ni * 8 + 2 * t]     = f2tf32(s[ni][2]);
                p1[ni * 8 + 2 * t + 1] = f2tf32(s[ni][3]);
            }
        }
        __syncwarp();

        // O += P @ V
        #pragma unroll
        for (int kk = 0; kk < 8; kk++) {
            uint32_t pa[4];
            const uint32_t* pr0 = Ps + (w * 16 + g) * FPS + kk * 8 + t;
            const uint32_t* pr1 = Ps + (w * 16 + 8 + g) * FPS + kk * 8 + t;
            pa[0] = pr0[0];
            pa[1] = pr1[0];
            pa[2] = pr0[4];
            pa[3] = pr1[4];
            #pragma unroll
            for (int ni = 0; ni < 16; ni++) {
                uint32_t vb[2];
                vb[0] = Vs[(kk * 8 + t) * FVS + ni * 8 + g];
                vb[1] = Vs[(kk * 8 + t + 4) * FVS + ni * 8 + g];
                mma_tf32(o_acc[ni], pa, vb);
            }
        }
    }

    // epilogue: normalize and store [B,H,S,DH] contiguous
    float inv0 = 1.f / l0r, inv1 = 1.f / l1r;
    size_t ob0 = (((size_t)b * NHEAD + h) * SEQ + (q0 + w * 16 + g)) * DHEAD;
    size_t ob1 = ob0 + (size_t)8 * DHEAD;
    #pragma unroll
    for (int ni = 0; ni < 16; ni++) {
        int cb = ni * 8 + 2 * t;
        *(float2*)(O + ob0 + cb) = make_float2(o_acc[ni][0] * inv0, o_acc[ni][1] * inv0);
        *(float2*)(O + ob1 + cb) = make_float2(o_acc[ni][2] * inv1, o_acc[ni][3] * inv1);
    }
}

// ============================================================
// out = LayerNorm(A + Bb) * gamma + beta   (row = 2048)
// ============================================================
__global__ void __launch_bounds__(256) add_ln_kernel(
    const float* __restrict__ A, const float* __restrict__ Bb,
    const float* __restrict__ gamma, const float* __restrict__ beta,
    float* __restrict__ out)
{
    const int row = blockIdx.x;
    const int tid = threadIdx.x;
    const float* a  = A  + (size_t)row * DMODEL;
    const float* bb = Bb + (size_t)row * DMODEL;

    float v[8];
    float s = 0.f, sq = 0.f;
    #pragma unroll
    for (int i = 0; i < 8; i++) {
        int idx = tid + i * 256;
        float x = a[idx] + bb[idx];
        v[i] = x;
        s += x;
        sq += x * x;
    }
    #pragma unroll
    for (int off = 16; off >= 1; off >>= 1) {
        s  += __shfl_xor_sync(0xffffffffu, s, off);
        sq += __shfl_xor_sync(0xffffffffu, sq, off);
    }
    __shared__ float red[2][8];
    __shared__ float fmean, finv;
    int wid = tid >> 5, lane = tid & 31;
    if (lane == 0) { red[0][wid] = s; red[1][wid] = sq; }
    __syncthreads();
    if (tid == 0) {
        float ts = 0.f, tq = 0.f;
        #pragma unroll
        for (int w = 0; w < 8; w++) { ts += red[0][w]; tq += red[1][w]; }
        float mean = ts * (1.f / DMODEL);
        float var = tq * (1.f / DMODEL) - mean * mean;
        fmean = mean;
        finv = rsqrtf(var + 1e-5f);
    }
    __syncthreads();
    float mean = fmean, inv = finv;
    float* op = out + (size_t)row * DMODEL;
    #pragma unroll
    for (int i = 0; i < 8; i++) {
        int idx = tid + i * 256;
        op[idx] = (v[i] - mean) * inv * gamma[idx] + beta[idx];
    }
}

// ============================================================
extern "C" void kernel_launch(void* const* d_in, const int* in_sizes, int n_in,
                              void* d_out, int out_size)
{
    const float* x     = (const float*)d_in[0];
    const float* wq    = (const float*)d_in[1];
    const float* bq    = (const float*)d_in[2];
    const float* wk    = (const float*)d_in[3];
    const float* bk    = (const float*)d_in[4];
    const float* wv    = (const float*)d_in[5];
    const float* bv    = (const float*)d_in[6];
    const float* wf    = (const float*)d_in[7];
    const float* bf    = (const float*)d_in[8];
    const float* gamma = (const float*)d_in[9];
    const float* beta  = (const float*)d_in[10];
    float* out = (float*)d_out;

    float *q, *k, *v, *o, *h1, *h2;
    cudaGetSymbolAddress((void**)&q,  g_q);
    cudaGetSymbolAddress((void**)&k,  g_k);
    cudaGetSymbolAddress((void**)&v,  g_v);
    cudaGetSymbolAddress((void**)&o,  g_o);
    cudaGetSymbolAddress((void**)&h1, g_h1);
    cudaGetSymbolAddress((void**)&h2, g_h2);

    const dim3 gemm_grid(DMODEL / TBN, MTOK / TBM);
    const size_t gemm_smem = 2 * STAGE_SIZE * sizeof(float);   // 71680
    const size_t fa_bytes = (size_t)(64 * FKS + 64 * FVS + 64 * FPS) * 4;  // 86016

    static int attr_done = 0;
    if (!attr_done) {
        cudaFuncSetAttribute(gemm_tf32_kernel,
                             cudaFuncAttributeMaxDynamicSharedMemorySize,
                             (int)gemm_smem);
        cudaFuncSetAttribute(flash_attn_tc_kernel,
                             cudaFuncAttributeMaxDynamicSharedMemorySize,
                             (int)fa_bytes);
        attr_done = 1;
    }

    gemm_tf32_kernel<<<gemm_grid, 256, gemm_smem>>>(x, wq, bq, q, MTOK, DMODEL, DMODEL);
    gemm_tf32_kernel<<<gemm_grid, 256, gemm_smem>>>(x, wk, bk, k, MTOK, DMODEL, DMODEL);
    gemm_tf32_kernel<<<gemm_grid, 256, gemm_smem>>>(x, wv, bv, v, MTOK, DMODEL, DMODEL);

    flash_attn_tc_kernel<<<dim3(SEQ / 64, NHEAD, BATCH), 128, fa_bytes>>>(q, k, v, o);

    add_ln_kernel<<<MTOK, 256>>>(o, x, gamma, beta, h1);
    gemm_tf32_kernel<<<gemm_grid, 256, gemm_smem>>>(h1, wf, bf, h2, MTOK, DMODEL, DMODEL);
    add_ln_kernel<<<MTOK, 256>>>(h2, o, gamma, beta, out);
}

// round 5
// speedup vs baseline: 4.3524x; 1.0485x over previous
#include <cuda_runtime.h>
#include <cstdint>

#define MTOK 4096      // B*S
#define DMODEL 2048
#define NHEAD 16
#define DHEAD 128
#define BATCH 2
#define SEQ 2048

// ---- scratch (no cudaMalloc allowed) ----
__device__ uint32_t g_xt[MTOK * DMODEL];      // tf32(x)
__device__ uint32_t g_wqt[DMODEL * DMODEL];
__device__ uint32_t g_wkt[DMODEL * DMODEL];
__device__ uint32_t g_wvt[DMODEL * DMODEL];
__device__ uint32_t g_wft[DMODEL * DMODEL];
__device__ uint32_t g_q[MTOK * DMODEL];       // tf32 bits
__device__ uint32_t g_k[MTOK * DMODEL];       // tf32 bits
__device__ uint32_t g_v[MTOK * DMODEL];       // tf32 bits
__device__ float    g_o[MTOK * DMODEL];       // [B,H,S,DH] contig == buggy flat view
__device__ uint32_t g_h1[MTOK * DMODEL];      // tf32 bits (feeds FF gemm only)
__device__ float    g_h2[MTOK * DMODEL];

extern __shared__ float g_smem[];

// ============================================================
// helpers
// ============================================================
__device__ __forceinline__ void cp_async16(uint32_t saddr, const void* gaddr) {
    asm volatile("cp.async.cg.shared.global [%0], [%1], 16;\n" :: "r"(saddr), "l"(gaddr));
}
__device__ __forceinline__ void cp_commit() {
    asm volatile("cp.async.commit_group;\n");
}
__device__ __forceinline__ uint32_t f2tf32(float x) {
    uint32_t r;
    asm("cvt.rna.tf32.f32 %0, %1;" : "=r"(r) : "f"(x));
    return r;
}
__device__ __forceinline__ void mma_tf32(float* c, const uint32_t* a, const uint32_t* b) {
    asm volatile(
        "mma.sync.aligned.m16n8k8.row.col.f32.tf32.tf32.f32 "
        "{%0,%1,%2,%3}, {%4,%5,%6,%7}, {%8,%9}, {%0,%1,%2,%3};\n"
        : "+f"(c[0]), "+f"(c[1]), "+f"(c[2]), "+f"(c[3])
        : "r"(a[0]), "r"(a[1]), "r"(a[2]), "r"(a[3]), "r"(b[0]), "r"(b[1]));
}

// ============================================================
// elementwise tf32 conversion (hoists ALL cvt out of hot loops)
// ============================================================
__global__ void __launch_bounds__(256) cvt_tf32_kernel(
    const float* __restrict__ in, uint32_t* __restrict__ out)
{
    int i = (blockIdx.x * 256 + threadIdx.x) * 4;
    float4 v = *(const float4*)(in + i);
    uint4 o = make_uint4(f2tf32(v.x), f2tf32(v.y), f2tf32(v.z), f2tf32(v.w));
    *(uint4*)(out + i) = o;
}

// ============================================================
// TF32 tensor-core GEMM: C[M,N] = A[M,K] @ W[K,N] + bias[N]
// A, W pre-converted tf32 bits. block 128x128x32, 8 warps, 2-stage cp.async.
// out_tf32 != 0 -> store tf32 bits (uint32), else fp32.
// ============================================================
#define TBM 128
#define TBN 128
#define TBK 32
#define AS_STRIDE 36
#define BS_STRIDE 136
#define AS_SIZE (TBM * AS_STRIDE)
#define BS_SIZE (TBK * BS_STRIDE)
#define STAGE_SIZE (AS_SIZE + BS_SIZE)

__global__ void __launch_bounds__(256, 2) gemm_tf32_kernel(
    const uint32_t* __restrict__ A, const uint32_t* __restrict__ W,
    const float* __restrict__ bias, void* __restrict__ Cout,
    int out_tf32)
{
    const int tid = threadIdx.x;
    const int wid = tid >> 5;
    const int lane = tid & 31;
    const int g = lane >> 2;
    const int t = lane & 3;
    const int wr = wid >> 2;
    const int wc = wid & 3;
    const int R = wr * 64;
    const int Cc = wc * 32;
    const int rowBase = blockIdx.y * TBM;
    const int colBase = blockIdx.x * TBN;
    const int K = DMODEL, N = DMODEL;

    uint32_t* stage[2] = { (uint32_t*)g_smem, (uint32_t*)g_smem + STAGE_SIZE };

    auto load_stage = [&](int s, int k0) {
        uint32_t* as = stage[s];
        uint32_t* bs = stage[s] + AS_SIZE;
        uint32_t as_u = (uint32_t)__cvta_generic_to_shared(as);
        uint32_t bs_u = (uint32_t)__cvta_generic_to_shared(bs);
        #pragma unroll
        for (int i = 0; i < 4; i++) {
            int c = tid + i * 256;
            int r  = c >> 3;
            int k4 = (c & 7) * 4;
            cp_async16(as_u + (uint32_t)(r * AS_STRIDE + k4) * 4,
                       A + (size_t)(rowBase + r) * K + k0 + k4);
        }
        #pragma unroll
        for (int i = 0; i < 4; i++) {
            int c = tid + i * 256;
            int r  = c >> 5;
            int n4 = (c & 31) * 4;
            cp_async16(bs_u + (uint32_t)(r * BS_STRIDE + n4) * 4,
                       W + (size_t)(k0 + r) * N + colBase + n4);
        }
        cp_commit();
    };

    float acc[4][4][4];
    #pragma unroll
    for (int mi = 0; mi < 4; mi++)
        #pragma unroll
        for (int ni = 0; ni < 4; ni++)
            #pragma unroll
            for (int r = 0; r < 4; r++) acc[mi][ni][r] = 0.f;

    const int T = K / TBK;
    load_stage(0, 0);

    int buf = 0;
    for (int it = 0; it < T; it++) {
        if (it + 1 < T) {
            load_stage(buf ^ 1, (it + 1) * TBK);
            asm volatile("cp.async.wait_group 1;\n");
        } else {
            asm volatile("cp.async.wait_group 0;\n");
        }
        __syncthreads();

        const uint32_t* as = stage[buf];
        const uint32_t* bs = stage[buf] + AS_SIZE;

        #pragma unroll
        for (int ks = 0; ks < 4; ks++) {
            const int kk = ks * 8;
            uint32_t af[4][4], bf[4][2];
            #pragma unroll
            for (int mi = 0; mi < 4; mi++) {
                int r0 = R + mi * 16 + g;
                af[mi][0] = as[r0 * AS_STRIDE + kk + t];
                af[mi][1] = as[(r0 + 8) * AS_STRIDE + kk + t];
                af[mi][2] = as[r0 * AS_STRIDE + kk + t + 4];
                af[mi][3] = as[(r0 + 8) * AS_STRIDE + kk + t + 4];
            }
            #pragma unroll
            for (int ni = 0; ni < 4; ni++) {
                int c0 = Cc + ni * 8 + g;
                bf[ni][0] = bs[(kk + t) * BS_STRIDE + c0];
                bf[ni][1] = bs[(kk + t + 4) * BS_STRIDE + c0];
            }
            #pragma unroll
            for (int mi = 0; mi < 4; mi++)
                #pragma unroll
                for (int ni = 0; ni < 4; ni++)
                    mma_tf32(acc[mi][ni], af[mi], bf[ni]);
        }
        __syncthreads();
        buf ^= 1;
    }

    #pragma unroll
    for (int mi = 0; mi < 4; mi++) {
        int r0 = rowBase + R + mi * 16 + g;
        #pragma unroll
        for (int ni = 0; ni < 4; ni++) {
            int cb = colBase + Cc + ni * 8 + 2 * t;
            float bx = bias[cb], by = bias[cb + 1];
            float v00 = acc[mi][ni][0] + bx, v01 = acc[mi][ni][1] + by;
            float v10 = acc[mi][ni][2] + bx, v11 = acc[mi][ni][3] + by;
            if (out_tf32) {
                uint32_t* Ct = (uint32_t*)Cout;
                *(uint2*)(Ct + (size_t)r0 * N + cb) = make_uint2(f2tf32(v00), f2tf32(v01));
                *(uint2*)(Ct + (size_t)(r0 + 8) * N + cb) = make_uint2(f2tf32(v10), f2tf32(v11));
            } else {
                float* Cf = (float*)Cout;
                *(float2*)(Cf + (size_t)r0 * N + cb) = make_float2(v00, v01);
                *(float2*)(Cf + (size_t)(r0 + 8) * N + cb) = make_float2(v10, v11);
            }
        }
    }
}

// ============================================================
// Tensor-core flash attention (tf32 bits in Q/K/V): BQ=64, BKV=64, DH=128
// scale applied to S post-mma; K/V staged via raw cp.async.
// ============================================================
#define FKS 132
#define FVS 136
#define FPS 68

__global__ void __launch_bounds__(128) flash_attn_tc_kernel(
    const uint32_t* __restrict__ Q, const uint32_t* __restrict__ K,
    const uint32_t* __restrict__ V, float* __restrict__ O)
{
    uint32_t* Ks = (uint32_t*)g_smem;          // [64][132] tf32 bits
    uint32_t* Vs = Ks + 64 * FKS;              // [64][136]
    uint32_t* Ps = Vs + 64 * FVS;              // [64][68]

    const int tid = threadIdx.x;
    const int w = tid >> 5;
    const int lane = tid & 31;
    const int g = lane >> 2;
    const int t = lane & 3;
    const int q0 = blockIdx.x * 64;
    const int h  = blockIdx.y;
    const int b  = blockIdx.z;
    const float scale = 0.088388347648318447f;  // 1/sqrt(128)
    const size_t base = (size_t)b * SEQ * DMODEL + (size_t)h * DHEAD;

    const uint32_t ks_u = (uint32_t)__cvta_generic_to_shared(Ks);
    const uint32_t vs_u = (uint32_t)__cvta_generic_to_shared(Vs);

    // Q fragments (raw tf32 bits, unscaled)
    uint32_t qa[16][4];
    {
        const uint32_t* Qp0 = Q + base + (size_t)(q0 + w * 16 + g) * DMODEL;
        const uint32_t* Qp1 = Qp0 + (size_t)8 * DMODEL;
        #pragma unroll
        for (int kk = 0; kk < 16; kk++) {
            qa[kk][0] = Qp0[kk * 8 + t];
            qa[kk][1] = Qp1[kk * 8 + t];
            qa[kk][2] = Qp0[kk * 8 + t + 4];
            qa[kk][3] = Qp1[kk * 8 + t + 4];
        }
    }

    float o_acc[16][4];
    #pragma unroll
    for (int ni = 0; ni < 16; ni++)
        #pragma unroll
        for (int r = 0; r < 4; r++) o_acc[ni][r] = 0.f;
    float m0r = -1e30f, m1r = -1e30f, l0r = 0.f, l1r = 0.f;

    for (int t0 = 0; t0 < SEQ; t0 += 64) {
        __syncthreads();
        // stage K,V raw via cp.async
        #pragma unroll
        for (int i = 0; i < 16; i++) {
            int f = tid + i * 128;
            int r = f >> 5, c4 = (f & 31) * 4;
            cp_async16(ks_u + (uint32_t)(r * FKS + c4) * 4,
                       K + base + (size_t)(t0 + r) * DMODEL + c4);
            cp_async16(vs_u + (uint32_t)(r * FVS + c4) * 4,
                       V + base + (size_t)(t0 + r) * DMODEL + c4);
        }
        cp_commit();
        asm volatile("cp.async.wait_group 0;\n");
        __syncthreads();

        float s[8][4];
        #pragma unroll
        for (int ni = 0; ni < 8; ni++)
            #pragma unroll
            for (int r = 0; r < 4; r++) s[ni][r] = 0.f;

        #pragma unroll
        for (int kk = 0; kk < 16; kk++) {
            #pragma unroll
            for (int ni = 0; ni < 8; ni++) {
                uint32_t bfr[2];
                const uint32_t* kr = Ks + (ni * 8 + g) * FKS + kk * 8 + t;
                bfr[0] = kr[0];
                bfr[1] = kr[4];
                mma_tf32(s[ni], qa[kk], bfr);
            }
        }

        // apply scale, then online softmax
        #pragma unroll
        for (int ni = 0; ni < 8; ni++) {
            s[ni][0] *= scale; s[ni][1] *= scale;
            s[ni][2] *= scale; s[ni][3] *= scale;
        }
        float mt0 = -1e30f, mt1 = -1e30f;
        #pragma unroll
        for (int ni = 0; ni < 8; ni++) {
            mt0 = fmaxf(mt0, fmaxf(s[ni][0], s[ni][1]));
            mt1 = fmaxf(mt1, fmaxf(s[ni][2], s[ni][3]));
        }
        #pragma unroll
        for (int off = 1; off <= 2; off <<= 1) {
            mt0 = fmaxf(mt0, __shfl_xor_sync(0xffffffffu, mt0, off));
            mt1 = fmaxf(mt1, __shfl_xor_sync(0xffffffffu, mt1, off));
        }
        float mn0 = fmaxf(m0r, mt0), mn1 = fmaxf(m1r, mt1);
        float c0 = __expf(m0r - mn0), c1 = __expf(m1r - mn1);
        float rs0 = 0.f, rs1 = 0.f;
        #pragma unroll
        for (int ni = 0; ni < 8; ni++) {
            s[ni][0] = __expf(s[ni][0] - mn0);
            s[ni][1] = __expf(s[ni][1] - mn0);
            s[ni][2] = __expf(s[ni][2] - mn1);
            s[ni][3] = __expf(s[ni][3] - mn1);
            rs0 += s[ni][0] + s[ni][1];
            rs1 += s[ni][2] + s[ni][3];
        }
        #pragma unroll
        for (int off = 1; off <= 2; off <<= 1) {
            rs0 += __shfl_xor_sync(0xffffffffu, rs0, off);
            rs1 += __shfl_xor_sync(0xffffffffu, rs1, off);
        }
        l0r = l0r * c0 + rs0;  m0r = mn0;
        l1r = l1r * c1 + rs1;  m1r = mn1;
        #pragma unroll
        for (int ni = 0; ni < 16; ni++) {
            o_acc[ni][0] *= c0; o_acc[ni][1] *= c0;
            o_acc[ni][2] *= c1; o_acc[ni][3] *= c1;
        }

        // stage P (tf32 RNA) into per-warp smem region
        {
            uint32_t* p0 = Ps + (w * 16 + g) * FPS;
            uint32_t* p1 = Ps + (w * 16 + 8 + g) * FPS;
            #pragma unroll
            for (int ni = 0; ni < 8; ni++) {
                p0[ni * 8 + 2 * t]     = f2tf32(s[ni][0]);
                p0[ni * 8 + 2 * t + 1] = f2tf32(s[ni][1]);
                p1[ni * 8 + 2 * t]     = f2tf32(s[ni][2]);
                p1[ni * 8 + 2 * t + 1] = f2tf32(s[ni][3]);
            }
        }
        __syncwarp();

        // O += P @ V
        #pragma unroll
        for (int kk = 0; kk < 8; kk++) {
            uint32_t pa[4];
            const uint32_t* pr0 = Ps + (w * 16 + g) * FPS + kk * 8 + t;
            const uint32_t* pr1 = Ps + (w * 16 + 8 + g) * FPS + kk * 8 + t;
            pa[0] = pr0[0];
            pa[1] = pr1[0];
            pa[2] = pr0[4];
            pa[3] = pr1[4];
            #pragma unroll
            for (int ni = 0; ni < 16; ni++) {
                uint32_t vb[2];
                vb[0] = Vs[(kk * 8 + t) * FVS + ni * 8 + g];
                vb[1] = Vs[(kk * 8 + t + 4) * FVS + ni * 8 + g];
                mma_tf32(o_acc[ni], pa, vb);
            }
        }
    }

    float inv0 = 1.f / l0r, inv1 = 1.f / l1r;
    size_t ob0 = (((size_t)b * NHEAD + h) * SEQ + (q0 + w * 16 + g)) * DHEAD;
    size_t ob1 = ob0 + (size_t)8 * DHEAD;
    #pragma unroll
    for (int ni = 0; ni < 16; ni++) {
        int cb = ni * 8 + 2 * t;
        *(float2*)(O + ob0 + cb) = make_float2(o_acc[ni][0] * inv0, o_acc[ni][1] * inv0);
        *(float2*)(O + ob1 + cb) = make_float2(o_acc[ni][2] * inv1, o_acc[ni][3] * inv1);
    }
}

// ============================================================
// out = LayerNorm(A + Bb) * gamma + beta   (row = 2048)
// OUT_TF32: emit tf32 bit pattern (for GEMM consumption)
// ============================================================
template <bool OUT_TF32>
__global__ void __launch_bounds__(256) add_ln_kernel(
    const float* __restrict__ A, const float* __restrict__ Bb,
    const float* __restrict__ gamma, const float* __restrict__ beta,
    void* __restrict__ outv)
{
    const int row = blockIdx.x;
    const int tid = threadIdx.x;
    const float* a  = A  + (size_t)row * DMODEL;
    const float* bb = Bb + (size_t)row * DMODEL;

    float v[8];
    float s = 0.f, sq = 0.f;
    #pragma unroll
    for (int i = 0; i < 8; i++) {
        int idx = tid + i * 256;
        float x = a[idx] + bb[idx];
        v[i] = x;
        s += x;
        sq += x * x;
    }
    #pragma unroll
    for (int off = 16; off >= 1; off >>= 1) {
        s  += __shfl_xor_sync(0xffffffffu, s, off);
        sq += __shfl_xor_sync(0xffffffffu, sq, off);
    }
    __shared__ float red[2][8];
    __shared__ float fmean, finv;
    int wid = tid >> 5, lane = tid & 31;
    if (lane == 0) { red[0][wid] = s; red[1][wid] = sq; }
    __syncthreads();
    if (tid == 0) {
        float ts = 0.f, tq = 0.f;
        #pragma unroll
        for (int w = 0; w < 8; w++) { ts += red[0][w]; tq += red[1][w]; }
        float mean = ts * (1.f / DMODEL);
        float var = tq * (1.f / DMODEL) - mean * mean;
        fmean = mean;
        finv = rsqrtf(var + 1e-5f);
    }
    __syncthreads();
    float mean = fmean, inv = finv;
    #pragma unroll
    for (int i = 0; i < 8; i++) {
        int idx = tid + i * 256;
        float r = (v[i] - mean) * inv * gamma[idx] + beta[idx];
        if (OUT_TF32) {
            ((uint32_t*)outv)[(size_t)row * DMODEL + idx] = f2tf32(r);
        } else {
            ((float*)outv)[(size_t)row * DMODEL + idx] = r;
        }
    }
}

// ============================================================
extern "C" void kernel_launch(void* const* d_in, const int* in_sizes, int n_in,
                              void* d_out, int out_size)
{
    const float* x     = (const float*)d_in[0];
    const float* wq    = (const float*)d_in[1];
    const float* bq    = (const float*)d_in[2];
    const float* wk    = (const float*)d_in[3];
    const float* bk    = (const float*)d_in[4];
    const float* wv    = (const float*)d_in[5];
    const float* bv    = (const float*)d_in[6];
    const float* wf    = (const float*)d_in[7];
    const float* bf    = (const float*)d_in[8];
    const float* gamma = (const float*)d_in[9];
    const float* beta  = (const float*)d_in[10];
    float* out = (float*)d_out;

    uint32_t *xt, *wqt, *wkt, *wvt, *wft, *q, *k, *v, *h1;
    float *o, *h2;
    cudaGetSymbolAddress((void**)&xt,  g_xt);
    cudaGetSymbolAddress((void**)&wqt, g_wqt);
    cudaGetSymbolAddress((void**)&wkt, g_wkt);
    cudaGetSymbolAddress((void**)&wvt, g_wvt);
    cudaGetSymbolAddress((void**)&wft, g_wft);
    cudaGetSymbolAddress((void**)&q,   g_q);
    cudaGetSymbolAddress((void**)&k,   g_k);
    cudaGetSymbolAddress((void**)&v,   g_v);
    cudaGetSymbolAddress((void**)&h1,  g_h1);
    cudaGetSymbolAddress((void**)&o,   g_o);
    cudaGetSymbolAddress((void**)&h2,  g_h2);

    const dim3 gemm_grid(DMODEL / TBN, MTOK / TBM);             // (16, 32)
    const size_t gemm_smem = 2 * STAGE_SIZE * sizeof(float);    // 71680
    const size_t fa_bytes = (size_t)(64 * FKS + 64 * FVS + 64 * FPS) * 4;  // 86016

    static int attr_done = 0;
    if (!attr_done) {
        cudaFuncSetAttribute(gemm_tf32_kernel,
                             cudaFuncAttributeMaxDynamicSharedMemorySize,
                             (int)gemm_smem);
        cudaFuncSetAttribute(flash_attn_tc_kernel,
                             cudaFuncAttributeMaxDynamicSharedMemorySize,
                             (int)fa_bytes);
        attr_done = 1;
    }

    // pre-convert operands to tf32 (once per launch; pure bandwidth)
    cvt_tf32_kernel<<<MTOK * DMODEL / 1024, 256>>>(x, xt);
    cvt_tf32_kernel<<<DMODEL * DMODEL / 1024, 256>>>(wq, wqt);
    cvt_tf32_kernel<<<DMODEL * DMODEL / 1024, 256>>>(wk, wkt);
    cvt_tf32_kernel<<<DMODEL * DMODEL / 1024, 256>>>(wv, wvt);
    cvt_tf32_kernel<<<DMODEL * DMODEL / 1024, 256>>>(wf, wft);

    gemm_tf32_kernel<<<gemm_grid, 256, gemm_smem>>>(xt, wqt, bq, q, 1);
    gemm_tf32_kernel<<<gemm_grid, 256, gemm_smem>>>(xt, wkt, bk, k, 1);
    gemm_tf32_kernel<<<gemm_grid, 256, gemm_smem>>>(xt, wvt, bv, v, 1);

    flash_attn_tc_kernel<<<dim3(SEQ / 64, NHEAD, BATCH), 128, fa_bytes>>>(q, k, v, o);

    add_ln_kernel<true><<<MTOK, 256>>>(o, x, gamma, beta, h1);
    gemm_tf32_kernel<<<gemm_grid, 256, gemm_smem>>>(h1, wft, bf, h2, 0);
    add_ln_kernel<false><<<MTOK, 256>>>(h2, o, gamma, beta, out);
}

// round 6
// speedup vs baseline: 4.6446x; 1.0671x over previous
#include <cuda_runtime.h>
#include <cstdint>

#define MTOK 4096      // B*S
#define DMODEL 2048
#define NHEAD 16
#define DHEAD 128
#define BATCH 2
#define SEQ 2048

// ---- scratch (no cudaMalloc allowed) ----
__device__ uint32_t g_xt[MTOK * DMODEL];      // tf32(x)
__device__ uint32_t g_wqt[DMODEL * DMODEL];
__device__ uint32_t g_wkt[DMODEL * DMODEL];
__device__ uint32_t g_wvt[DMODEL * DMODEL];
__device__ uint32_t g_wft[DMODEL * DMODEL];
__device__ uint32_t g_q[MTOK * DMODEL];       // tf32 bits
__device__ uint32_t g_k[MTOK * DMODEL];       // tf32 bits
__device__ uint32_t g_v[MTOK * DMODEL];       // tf32 bits
__device__ float    g_o[MTOK * DMODEL];       // [B,H,S,DH] contig == buggy flat view
__device__ uint32_t g_h1[MTOK * DMODEL];      // tf32 bits (feeds FF gemm only)
__device__ float    g_h2[MTOK * DMODEL];

extern __shared__ float g_smem[];

// ============================================================
// helpers
// ============================================================
__device__ __forceinline__ void cp_async16(uint32_t saddr, const void* gaddr) {
    asm volatile("cp.async.cg.shared.global [%0], [%1], 16;\n" :: "r"(saddr), "l"(gaddr));
}
__device__ __forceinline__ void cp_commit() {
    asm volatile("cp.async.commit_group;\n");
}
__device__ __forceinline__ uint32_t f2tf32(float x) {
    uint32_t r;
    asm("cvt.rna.tf32.f32 %0, %1;" : "=r"(r) : "f"(x));
    return r;
}
__device__ __forceinline__ void mma_tf32(float* c, const uint32_t* a, const uint32_t* b) {
    asm volatile(
        "mma.sync.aligned.m16n8k8.row.col.f32.tf32.tf32.f32 "
        "{%0,%1,%2,%3}, {%4,%5,%6,%7}, {%8,%9}, {%0,%1,%2,%3};\n"
        : "+f"(c[0]), "+f"(c[1]), "+f"(c[2]), "+f"(c[3])
        : "r"(a[0]), "r"(a[1]), "r"(a[2]), "r"(a[3]), "r"(b[0]), "r"(b[1]));
}

// ============================================================
// elementwise tf32 conversion (hoists ALL cvt out of hot loops)
// ============================================================
__global__ void __launch_bounds__(256) cvt_tf32_kernel(
    const float* __restrict__ in, uint32_t* __restrict__ out)
{
    int i = (blockIdx.x * 256 + threadIdx.x) * 4;
    float4 v = *(const float4*)(in + i);
    uint4 o = make_uint4(f2tf32(v.x), f2tf32(v.y), f2tf32(v.z), f2tf32(v.w));
    *(uint4*)(out + i) = o;
}

// ============================================================
// TF32 tensor-core GEMM: C[M,N] = A[M,K] @ W[K,N] + bias[N]
// (unchanged — at the legacy tf32 tensor-pipe ceiling)
// ============================================================
#define TBM 128
#define TBN 128
#define TBK 32
#define AS_STRIDE 36
#define BS_STRIDE 136
#define AS_SIZE (TBM * AS_STRIDE)
#define BS_SIZE (TBK * BS_STRIDE)
#define STAGE_SIZE (AS_SIZE + BS_SIZE)

__global__ void __launch_bounds__(256, 2) gemm_tf32_kernel(
    const uint32_t* __restrict__ A, const uint32_t* __restrict__ W,
    const float* __restrict__ bias, void* __restrict__ Cout,
    int out_tf32)
{
    const int tid = threadIdx.x;
    const int wid = tid >> 5;
    const int lane = tid & 31;
    const int g = lane >> 2;
    const int t = lane & 3;
    const int wr = wid >> 2;
    const int wc = wid & 3;
    const int R = wr * 64;
    const int Cc = wc * 32;
    const int rowBase = blockIdx.y * TBM;
    const int colBase = blockIdx.x * TBN;
    const int K = DMODEL, N = DMODEL;

    uint32_t* stage[2] = { (uint32_t*)g_smem, (uint32_t*)g_smem + STAGE_SIZE };

    auto load_stage = [&](int s, int k0) {
        uint32_t* as = stage[s];
        uint32_t* bs = stage[s] + AS_SIZE;
        uint32_t as_u = (uint32_t)__cvta_generic_to_shared(as);
        uint32_t bs_u = (uint32_t)__cvta_generic_to_shared(bs);
        #pragma unroll
        for (int i = 0; i < 4; i++) {
            int c = tid + i * 256;
            int r  = c >> 3;
            int k4 = (c & 7) * 4;
            cp_async16(as_u + (uint32_t)(r * AS_STRIDE + k4) * 4,
                       A + (size_t)(rowBase + r) * K + k0 + k4);
        }
        #pragma unroll
        for (int i = 0; i < 4; i++) {
            int c = tid + i * 256;
            int r  = c >> 5;
            int n4 = (c & 31) * 4;
            cp_async16(bs_u + (uint32_t)(r * BS_STRIDE + n4) * 4,
                       W + (size_t)(k0 + r) * N + colBase + n4);
        }
        cp_commit();
    };

    float acc[4][4][4];
    #pragma unroll
    for (int mi = 0; mi < 4; mi++)
        #pragma unroll
        for (int ni = 0; ni < 4; ni++)
            #pragma unroll
            for (int r = 0; r < 4; r++) acc[mi][ni][r] = 0.f;

    const int T = K / TBK;
    load_stage(0, 0);

    int buf = 0;
    for (int it = 0; it < T; it++) {
        if (it + 1 < T) {
            load_stage(buf ^ 1, (it + 1) * TBK);
            asm volatile("cp.async.wait_group 1;\n");
        } else {
            asm volatile("cp.async.wait_group 0;\n");
        }
        __syncthreads();

        const uint32_t* as = stage[buf];
        const uint32_t* bs = stage[buf] + AS_SIZE;

        #pragma unroll
        for (int ks = 0; ks < 4; ks++) {
            const int kk = ks * 8;
            uint32_t af[4][4], bf[4][2];
            #pragma unroll
            for (int mi = 0; mi < 4; mi++) {
                int r0 = R + mi * 16 + g;
                af[mi][0] = as[r0 * AS_STRIDE + kk + t];
                af[mi][1] = as[(r0 + 8) * AS_STRIDE + kk + t];
                af[mi][2] = as[r0 * AS_STRIDE + kk + t + 4];
                af[mi][3] = as[(r0 + 8) * AS_STRIDE + kk + t + 4];
            }
            #pragma unroll
            for (int ni = 0; ni < 4; ni++) {
                int c0 = Cc + ni * 8 + g;
                bf[ni][0] = bs[(kk + t) * BS_STRIDE + c0];
                bf[ni][1] = bs[(kk + t + 4) * BS_STRIDE + c0];
            }
            #pragma unroll
            for (int mi = 0; mi < 4; mi++)
                #pragma unroll
                for (int ni = 0; ni < 4; ni++)
                    mma_tf32(acc[mi][ni], af[mi], bf[ni]);
        }
        __syncthreads();
        buf ^= 1;
    }

    #pragma unroll
    for (int mi = 0; mi < 4; mi++) {
        int r0 = rowBase + R + mi * 16 + g;
        #pragma unroll
        for (int ni = 0; ni < 4; ni++) {
            int cb = colBase + Cc + ni * 8 + 2 * t;
            float bx = bias[cb], by = bias[cb + 1];
            float v00 = acc[mi][ni][0] + bx, v01 = acc[mi][ni][1] + by;
            float v10 = acc[mi][ni][2] + bx, v11 = acc[mi][ni][3] + by;
            if (out_tf32) {
                uint32_t* Ct = (uint32_t*)Cout;
                *(uint2*)(Ct + (size_t)r0 * N + cb) = make_uint2(f2tf32(v00), f2tf32(v01));
                *(uint2*)(Ct + (size_t)(r0 + 8) * N + cb) = make_uint2(f2tf32(v10), f2tf32(v11));
            } else {
                float* Cf = (float*)Cout;
                *(float2*)(Cf + (size_t)r0 * N + cb) = make_float2(v00, v01);
                *(float2*)(Cf + (size_t)(r0 + 8) * N + cb) = make_float2(v10, v11);
            }
        }
    }
}

// ============================================================
// Tensor-core flash attention v2: BQ=128 (8 warps), BKV=64,
// double-buffered cp.async K/V staging. tf32 bits in Q/K/V.
// ============================================================
#define FKS 132
#define FVS 136
#define FPS 68
#define KV_STAGE (64 * FKS + 64 * FVS)    // uint32s per stage = 17152

__global__ void __launch_bounds__(256) flash_attn_tc_kernel(
    const uint32_t* __restrict__ Q, const uint32_t* __restrict__ K,
    const uint32_t* __restrict__ V, float* __restrict__ O)
{
    uint32_t* S0 = (uint32_t*)g_smem;               // stage 0: K[64][132], V[64][136]
    uint32_t* S1 = S0 + KV_STAGE;                   // stage 1
    uint32_t* Ps = S1 + KV_STAGE;                   // P [128][68]

    const int tid = threadIdx.x;
    const int w = tid >> 5;          // 0..7
    const int lane = tid & 31;
    const int g = lane >> 2;
    const int t = lane & 3;
    const int q0 = blockIdx.x * 128;
    const int h  = blockIdx.y;
    const int b  = blockIdx.z;
    const float scale = 0.088388347648318447f;  // 1/sqrt(128)
    const size_t base = (size_t)b * SEQ * DMODEL + (size_t)h * DHEAD;

    const uint32_t s0_u = (uint32_t)__cvta_generic_to_shared(S0);
    const uint32_t s1_u = (uint32_t)__cvta_generic_to_shared(S1);

    // issue K/V tile load into stage s for kv block starting at t0
    auto stage_kv = [&](uint32_t su, int t0) {
        #pragma unroll
        for (int i = 0; i < 8; i++) {
            int f = tid + i * 256;               // 0..2047
            int r = f >> 5, c4 = (f & 31) * 4;
            cp_async16(su + (uint32_t)(r * FKS + c4) * 4,
                       K + base + (size_t)(t0 + r) * DMODEL + c4);
            cp_async16(su + (uint32_t)(64 * FKS + r * FVS + c4) * 4,
                       V + base + (size_t)(t0 + r) * DMODEL + c4);
        }
        cp_commit();
    };

    // Q fragments (raw tf32 bits, unscaled); warp w owns rows q0+16w+g, +8
    uint32_t qa[16][4];
    {
        const uint32_t* Qp0 = Q + base + (size_t)(q0 + w * 16 + g) * DMODEL;
        const uint32_t* Qp1 = Qp0 + (size_t)8 * DMODEL;
        #pragma unroll
        for (int kk = 0; kk < 16; kk++) {
            qa[kk][0] = Qp0[kk * 8 + t];
            qa[kk][1] = Qp1[kk * 8 + t];
            qa[kk][2] = Qp0[kk * 8 + t + 4];
            qa[kk][3] = Qp1[kk * 8 + t + 4];
        }
    }

    float o_acc[16][4];
    #pragma unroll
    for (int ni = 0; ni < 16; ni++)
        #pragma unroll
        for (int r = 0; r < 4; r++) o_acc[ni][r] = 0.f;
    float m0r = -1e30f, m1r = -1e30f, l0r = 0.f, l1r = 0.f;

    stage_kv(s0_u, 0);
    asm volatile("cp.async.wait_group 0;\n");
    __syncthreads();

    for (int it = 0; it < SEQ / 64; it++) {
        const uint32_t* Ks = (it & 1) ? S1 : S0;
        const uint32_t* Vs = Ks + 64 * FKS;
        // prefetch next tile into the other stage
        if (it + 1 < SEQ / 64) {
            stage_kv((it & 1) ? s0_u : s1_u, (it + 1) * 64);
        }

        // S = Q K^T
        float s[8][4];
        #pragma unroll
        for (int ni = 0; ni < 8; ni++)
            #pragma unroll
            for (int r = 0; r < 4; r++) s[ni][r] = 0.f;

        #pragma unroll
        for (int kk = 0; kk < 16; kk++) {
            #pragma unroll
            for (int ni = 0; ni < 8; ni++) {
                uint32_t bfr[2];
                const uint32_t* kr = Ks + (ni * 8 + g) * FKS + kk * 8 + t;
                bfr[0] = kr[0];
                bfr[1] = kr[4];
                mma_tf32(s[ni], qa[kk], bfr);
            }
        }

        // scale + online softmax
        #pragma unroll
        for (int ni = 0; ni < 8; ni++) {
            s[ni][0] *= scale; s[ni][1] *= scale;
            s[ni][2] *= scale; s[ni][3] *= scale;
        }
        float mt0 = -1e30f, mt1 = -1e30f;
        #pragma unroll
        for (int ni = 0; ni < 8; ni++) {
            mt0 = fmaxf(mt0, fmaxf(s[ni][0], s[ni][1]));
            mt1 = fmaxf(mt1, fmaxf(s[ni][2], s[ni][3]));
        }
        #pragma unroll
        for (int off = 1; off <= 2; off <<= 1) {
            mt0 = fmaxf(mt0, __shfl_xor_sync(0xffffffffu, mt0, off));
            mt1 = fmaxf(mt1, __shfl_xor_sync(0xffffffffu, mt1, off));
        }
        float mn0 = fmaxf(m0r, mt0), mn1 = fmaxf(m1r, mt1);
        float c0 = __expf(m0r - mn0), c1 = __expf(m1r - mn1);
        float rs0 = 0.f, rs1 = 0.f;
        #pragma unroll
        for (int ni = 0; ni < 8; ni++) {
            s[ni][0] = __expf(s[ni][0] - mn0);
            s[ni][1] = __expf(s[ni][1] - mn0);
            s[ni][2] = __expf(s[ni][2] - mn1);
            s[ni][3] = __expf(s[ni][3] - mn1);
            rs0 += s[ni][0] + s[ni][1];
            rs1 += s[ni][2] + s[ni][3];
        }
        #pragma unroll
        for (int off = 1; off <= 2; off <<= 1) {
            rs0 += __shfl_xor_sync(0xffffffffu, rs0, off);
            rs1 += __shfl_xor_sync(0xffffffffu, rs1, off);
        }
        l0r = l0r * c0 + rs0;  m0r = mn0;
        l1r = l1r * c1 + rs1;  m1r = mn1;
        #pragma unroll
        for (int ni = 0; ni < 16; ni++) {
            o_acc[ni][0] *= c0; o_acc[ni][1] *= c0;
            o_acc[ni][2] *= c1; o_acc[ni][3] *= c1;
        }

        // stage P (tf32 RNA) into per-warp region
        {
            uint32_t* p0 = Ps + (w * 16 + g) * FPS;
            uint32_t* p1 = Ps + (w * 16 + 8 + g) * FPS;
            #pragma unroll
            for (int ni = 0; ni < 8; ni++) {
                p0[ni * 8 + 2 * t]     = f2tf32(s[ni][0]);
                p0[ni * 8 + 2 * t + 1] = f2tf32(s[ni][1]);
                p1[ni * 8 + 2 * t]     = f2tf32(s[ni][2]);
                p1[ni * 8 + 2 * t + 1] = f2tf32(s[ni][3]);
            }
        }
        __syncwarp();

        // O += P @ V
        #pragma unroll
        for (int kk = 0; kk < 8; kk++) {
            uint32_t pa[4];
            const uint32_t* pr0 = Ps + (w * 16 + g) * FPS + kk * 8 + t;
            const uint32_t* pr1 = Ps + (w * 16 + 8 + g) * FPS + kk * 8 + t;
            pa[0] = pr0[0];
            pa[1] = pr1[0];
            pa[2] = pr0[4];
            pa[3] = pr1[4];
            #pragma unroll
            for (int ni = 0; ni < 16; ni++) {
                uint32_t vb[2];
                vb[0] = Vs[(kk * 8 + t) * FVS + ni * 8 + g];
                vb[1] = Vs[(kk * 8 + t + 4) * FVS + ni * 8 + g];
                mma_tf32(o_acc[ni], pa, vb);
            }
        }

        // next tile must be resident before anyone computes on it;
        // also fences current buffer reads before it is overwritten (it+2)
        asm volatile("cp.async.wait_group 0;\n");
        __syncthreads();
    }

    float inv0 = 1.f / l0r, inv1 = 1.f / l1r;
    size_t ob0 = (((size_t)b * NHEAD + h) * SEQ + (q0 + w * 16 + g)) * DHEAD;
    size_t ob1 = ob0 + (size_t)8 * DHEAD;
    #pragma unroll
    for (int ni = 0; ni < 16; ni++) {
        int cb = ni * 8 + 2 * t;
        *(float2*)(O + ob0 + cb) = make_float2(o_acc[ni][0] * inv0, o_acc[ni][1] * inv0);
        *(float2*)(O + ob1 + cb) = make_float2(o_acc[ni][2] * inv1, o_acc[ni][3] * inv1);
    }
}

// ============================================================
// out = LayerNorm(A + Bb) * gamma + beta   (row = 2048)
// ============================================================
template <bool OUT_TF32>
__global__ void __launch_bounds__(256) add_ln_kernel(
    const float* __restrict__ A, const float* __restrict__ Bb,
    const float* __restrict__ gamma, const float* __restrict__ beta,
    void* __restrict__ outv)
{
    const int row = blockIdx.x;
    const int tid = threadIdx.x;
    const float* a  = A  + (size_t)row * DMODEL;
    const float* bb = Bb + (size_t)row * DMODEL;

    float v[8];
    float s = 0.f, sq = 0.f;
    #pragma unroll
    for (int i = 0; i < 8; i++) {
        int idx = tid + i * 256;
        float x = a[idx] + bb[idx];
        v[i] = x;
        s += x;
        sq += x * x;
    }
    #pragma unroll
    for (int off = 16; off >= 1; off >>= 1) {
        s  += __shfl_xor_sync(0xffffffffu, s, off);
        sq += __shfl_xor_sync(0xffffffffu, sq, off);
    }
    __shared__ float red[2][8];
    __shared__ float fmean, finv;
    int wid = tid >> 5, lane = tid & 31;
    if (lane == 0) { red[0][wid] = s; red[1][wid] = sq; }
    __syncthreads();
    if (tid == 0) {
        float ts = 0.f, tq = 0.f;
        #pragma unroll
        for (int w = 0; w < 8; w++) { ts += red[0][w]; tq += red[1][w]; }
        float mean = ts * (1.f / DMODEL);
        float var = tq * (1.f / DMODEL) - mean * mean;
        fmean = mean;
        finv = rsqrtf(var + 1e-5f);
    }
    __syncthreads();
    float mean = fmean, inv = finv;
    #pragma unroll
    for (int i = 0; i < 8; i++) {
        int idx = tid + i * 256;
        float r = (v[i] - mean) * inv * gamma[idx] + beta[idx];
        if (OUT_TF32) {
            ((uint32_t*)outv)[(size_t)row * DMODEL + idx] = f2tf32(r);
        } else {
            ((float*)outv)[(size_t)row * DMODEL + idx] = r;
        }
    }
}

// ============================================================
extern "C" void kernel_launch(void* const* d_in, const int* in_sizes, int n_in,
                              void* d_out, int out_size)
{
    const float* x     = (const float*)d_in[0];
    const float* wq    = (const float*)d_in[1];
    const float* bq    = (const float*)d_in[2];
    const float* wk    = (const float*)d_in[3];
    const float* bk    = (const float*)d_in[4];
    const float* wv    = (const float*)d_in[5];
    const float* bv    = (const float*)d_in[6];
    const float* wf    = (const float*)d_in[7];
    const float* bf    = (const float*)d_in[8];
    const float* gamma = (const float*)d_in[9];
    const float* beta  = (const float*)d_in[10];
    float* out = (float*)d_out;

    uint32_t *xt, *wqt, *wkt, *wvt, *wft, *q, *k, *v, *h1;
    float *o, *h2;
    cudaGetSymbolAddress((void**)&xt,  g_xt);
    cudaGetSymbolAddress((void**)&wqt, g_wqt);
    cudaGetSymbolAddress((void**)&wkt, g_wkt);
    cudaGetSymbolAddress((void**)&wvt, g_wvt);
    cudaGetSymbolAddress((void**)&wft, g_wft);
    cudaGetSymbolAddress((void**)&q,   g_q);
    cudaGetSymbolAddress((void**)&k,   g_k);
    cudaGetSymbolAddress((void**)&v,   g_v);
    cudaGetSymbolAddress((void**)&h1,  g_h1);
    cudaGetSymbolAddress((void**)&o,   g_o);
    cudaGetSymbolAddress((void**)&h2,  g_h2);

    const dim3 gemm_grid(DMODEL / TBN, MTOK / TBM);             // (16, 32)
    const size_t gemm_smem = 2 * STAGE_SIZE * sizeof(float);    // 71680
    const size_t fa_bytes = (size_t)(2 * KV_STAGE + 128 * FPS) * 4;  // 172032

    static int attr_done = 0;
    if (!attr_done) {
        cudaFuncSetAttribute(gemm_tf32_kernel,
                             cudaFuncAttributeMaxDynamicSharedMemorySize,
                             (int)gemm_smem);
        cudaFuncSetAttribute(flash_attn_tc_kernel,
                             cudaFuncAttributeMaxDynamicSharedMemorySize,
                             (int)fa_bytes);
        attr_done = 1;
    }

    // pre-convert operands to tf32 (once per launch; pure bandwidth)
    cvt_tf32_kernel<<<MTOK * DMODEL / 1024, 256>>>(x, xt);
    cvt_tf32_kernel<<<DMODEL * DMODEL / 1024, 256>>>(wq, wqt);
    cvt_tf32_kernel<<<DMODEL * DMODEL / 1024, 256>>>(wk, wkt);
    cvt_tf32_kernel<<<DMODEL * DMODEL / 1024, 256>>>(wv, wvt);
    cvt_tf32_kernel<<<DMODEL * DMODEL / 1024, 256>>>(wf, wft);

    gemm_tf32_kernel<<<gemm_grid, 256, gemm_smem>>>(xt, wqt, bq, q, 1);
    gemm_tf32_kernel<<<gemm_grid, 256, gemm_smem>>>(xt, wkt, bk, k, 1);
    gemm_tf32_kernel<<<gemm_grid, 256, gemm_smem>>>(xt, wvt, bv, v, 1);

    flash_attn_tc_kernel<<<dim3(SEQ / 128, NHEAD, BATCH), 256, fa_bytes>>>(q, k, v, o);

    add_ln_kernel<true><<<MTOK, 256>>>(o, x, gamma, beta, h1);
    gemm_tf32_kernel<<<gemm_grid, 256, gemm_smem>>>(h1, wft, bf, h2, 0);
    add_ln_kernel<false><<<MTOK, 256>>>(h2, o, gamma, beta, out);
}

// round 8
// speedup vs baseline: 7.5958x; 1.6354x over previous
#include <cuda_runtime.h>
#include <cuda_fp16.h>
#include <cstdint>

#define MTOK 4096      // B*S
#define DMODEL 2048
#define NHEAD 16
#define DHEAD 128
#define BATCH 2
#define SEQ 2048

// ---- scratch (no cudaMalloc allowed) ----
__device__ __half  g_xh[MTOK * DMODEL];        // half(x) [M][K]
__device__ __half  g_wqt[DMODEL * DMODEL];     // W^T [N][K] half
__device__ __half  g_wkt[DMODEL * DMODEL];
__device__ __half  g_wvt[DMODEL * DMODEL];
__device__ __half  g_wft[DMODEL * DMODEL];
__device__ __half  g_q[MTOK * DMODEL];         // [M][N] half
__device__ __half  g_k[MTOK * DMODEL];         // [M][N] half
__device__ __half  g_vt[MTOK * DMODEL];        // V^T per head: [b][h][dh][s]
__device__ __half  g_h1[MTOK * DMODEL];        // half (feeds FF gemm)
__device__ float   g_o[MTOK * DMODEL];         // [B,H,S,DH] contig == buggy flat view
__device__ float   g_h2[MTOK * DMODEL];

extern __shared__ float g_smem[];

// ============================================================
// helpers
// ============================================================
__device__ __forceinline__ void cp_async16(uint32_t saddr, const void* gaddr) {
    asm volatile("cp.async.cg.shared.global [%0], [%1], 16;\n" :: "r"(saddr), "l"(gaddr));
}
__device__ __forceinline__ void cp_commit() {
    asm volatile("cp.async.commit_group;\n");
}
__device__ __forceinline__ uint32_t pack_h2(float a, float b) {
    __half2 h = __floats2half2_rn(a, b);
    return *(uint32_t*)&h;
}
__device__ __forceinline__ void mma_f16(float* c, const uint32_t* a, const uint32_t* b) {
    asm volatile(
        "mma.sync.aligned.m16n8k16.row.col.f32.f16.f16.f32 "
        "{%0,%1,%2,%3}, {%4,%5,%6,%7}, {%8,%9}, {%0,%1,%2,%3};\n"
        : "+f"(c[0]), "+f"(c[1]), "+f"(c[2]), "+f"(c[3])
        : "r"(a[0]), "r"(a[1]), "r"(a[2]), "r"(a[3]), "r"(b[0]), "r"(b[1]));
}

// ============================================================
// pre-pass: x -> half (same layout)
// ============================================================
__global__ void __launch_bounds__(256) cvt_half_kernel(
    const float* __restrict__ in, __half* __restrict__ out)
{
    int i = (blockIdx.x * 256 + threadIdx.x) * 8;
    float4 v0 = *(const float4*)(in + i);
    float4 v1 = *(const float4*)(in + i + 4);
    uint4 o;
    o.x = pack_h2(v0.x, v0.y);
    o.y = pack_h2(v0.z, v0.w);
    o.z = pack_h2(v1.x, v1.y);
    o.w = pack_h2(v1.z, v1.w);
    *(uint4*)((__half*)out + i) = o;
}

// pre-pass: W [K][N] fp32 -> W^T [N][K] half (smem transpose)
__global__ void __launch_bounds__(256) cvt_transpose_kernel(
    const float* __restrict__ in, __half* __restrict__ out)
{
    __shared__ __half tile[32][33];
    const int n0 = blockIdx.x * 32;
    const int k0 = blockIdx.y * 32;
    const int tx = threadIdx.x & 31;
    const int ty = threadIdx.x >> 5;   // 0..7
    #pragma unroll
    for (int i = 0; i < 32; i += 8)
        tile[ty + i][tx] = __float2half_rn(in[(size_t)(k0 + ty + i) * DMODEL + n0 + tx]);
    __syncthreads();
    #pragma unroll
    for (int i = 0; i < 32; i += 8)
        out[(size_t)(n0 + ty + i) * DMODEL + k0 + tx] = tile[tx][ty + i];
}

// ============================================================
// FP16 tensor-core GEMM: C[M,N] = A[M,K](half) @ Wt[N,K](half)^T + bias
// block 128x128x32, 8 warps (64x32 warp tiles), 2-stage cp.async
// out_mode: 0 = fp32 [M][N], 1 = half [M][N], 2 = half V^T per-head
// ============================================================
#define TBM 128
#define TBN 128
#define TBK 32
#define HS 40                         // smem row stride in halfs (80B, 16B-mult)
#define HTILE (128 * HS)              // halfs per tile
#define HSTAGE (2 * HTILE)            // A+B halfs per stage

__global__ void __launch_bounds__(256, 2) gemm_f16_kernel(
    const __half* __restrict__ A, const __half* __restrict__ Wt,
    const float* __restrict__ bias, void* __restrict__ Cout,
    int out_mode)
{
    const int tid = threadIdx.x;
    const int wid = tid >> 5;
    const int lane = tid & 31;
    const int g = lane >> 2;
    const int t = lane & 3;
    const int wr = wid >> 2;
    const int wc = wid & 3;
    const int R = wr * 64;
    const int Cc = wc * 32;
    const int rowBase = blockIdx.y * TBM;
    const int colBase = blockIdx.x * TBN;
    const int K = DMODEL, N = DMODEL;

    __half* stage[2] = { (__half*)g_smem, (__half*)g_smem + HSTAGE };

    auto load_stage = [&](int s, int k0) {
        __half* as = stage[s];
        __half* bs = stage[s] + HTILE;
        uint32_t as_u = (uint32_t)__cvta_generic_to_shared(as);
        uint32_t bs_u = (uint32_t)__cvta_generic_to_shared(bs);
        #pragma unroll
        for (int i = 0; i < 2; i++) {
            int c = tid + i * 256;          // 0..511
            int r = c >> 2;                 // 0..127
            int o = c & 3;                  // 16B chunk (8 halfs)
            cp_async16(as_u + (uint32_t)(r * HS + o * 8) * 2,
                       A + (size_t)(rowBase + r) * K + k0 + o * 8);
        }
        #pragma unroll
        for (int i = 0; i < 2; i++) {
            int c = tid + i * 256;
            int n = c >> 2;
            int o = c & 3;
            cp_async16(bs_u + (uint32_t)(n * HS + o * 8) * 2,
                       Wt + (size_t)(colBase + n) * K + k0 + o * 8);
        }
        cp_commit();
    };

    float acc[4][4][4];
    #pragma unroll
    for (int mi = 0; mi < 4; mi++)
        #pragma unroll
        for (int ni = 0; ni < 4; ni++)
            #pragma unroll
            for (int r = 0; r < 4; r++) acc[mi][ni][r] = 0.f;

    const int T = K / TBK;   // 64
    load_stage(0, 0);

    int buf = 0;
    for (int it = 0; it < T; it++) {
        if (it + 1 < T) {
            load_stage(buf ^ 1, (it + 1) * TBK);
            asm volatile("cp.async.wait_group 1;\n");
        } else {
            asm volatile("cp.async.wait_group 0;\n");
        }
        __syncthreads();

        const __half* as = stage[buf];
        const __half* bs = stage[buf] + HTILE;

        #pragma unroll
        for (int ks = 0; ks < 2; ks++) {
            const int kk = ks * 16;
            uint32_t af[4][4], bf[4][2];
            #pragma unroll
            for (int mi = 0; mi < 4; mi++) {
                int r0 = R + mi * 16 + g;
                af[mi][0] = *(const uint32_t*)&as[r0 * HS + kk + 2 * t];
                af[mi][1] = *(const uint32_t*)&as[(r0 + 8) * HS + kk + 2 * t];
                af[mi][2] = *(const uint32_t*)&as[r0 * HS + kk + 2 * t + 8];
                af[mi][3] = *(const uint32_t*)&as[(r0 + 8) * HS + kk + 2 * t + 8];
            }
            #pragma unroll
            for (int ni = 0; ni < 4; ni++) {
                int c0 = Cc + ni * 8 + g;
                bf[ni][0] = *(const uint32_t*)&bs[c0 * HS + kk + 2 * t];
                bf[ni][1] = *(const uint32_t*)&bs[c0 * HS + kk + 2 * t + 8];
            }
            #pragma unroll
            for (int mi = 0; mi < 4; mi++)
                #pragma unroll
                for (int ni = 0; ni < 4; ni++)
                    mma_f16(acc[mi][ni], af[mi], bf[ni]);
        }
        __syncthreads();
        buf ^= 1;
    }

    #pragma unroll
    for (int mi = 0; mi < 4; mi++) {
        int r0 = rowBase + R + mi * 16 + g;
        #pragma unroll
        for (int ni = 0; ni < 4; ni++) {
            int cb = colBase + Cc + ni * 8 + 2 * t;
            float bx = bias[cb], by = bias[cb + 1];
            float v00 = acc[mi][ni][0] + bx, v01 = acc[mi][ni][1] + by;
            float v10 = acc[mi][ni][2] + bx, v11 = acc[mi][ni][3] + by;
            if (out_mode == 0) {
                float* Cf = (float*)Cout;
                *(float2*)(Cf + (size_t)r0 * N + cb) = make_float2(v00, v01);
                *(float2*)(Cf + (size_t)(r0 + 8) * N + cb) = make_float2(v10, v11);
            } else if (out_mode == 1) {
                __half* Ch = (__half*)Cout;
                *(uint32_t*)(Ch + (size_t)r0 * N + cb) = pack_h2(v00, v01);
                *(uint32_t*)(Ch + (size_t)(r0 + 8) * N + cb) = pack_h2(v10, v11);
            } else {
                // V^T per head: (m, n) -> [b][h][dh][s]; b=m>>11, s=m&2047
                __half* Ct = (__half*)Cout;
                int b0 = r0 >> 11, s0 = r0 & 2047;
                int b1 = (r0 + 8) >> 11, s1 = (r0 + 8) & 2047;
                int h = cb >> 7, dh = cb & 127;
                size_t base0 = ((size_t)(b0 * NHEAD + h) * DHEAD + dh) * SEQ;
                size_t base1 = ((size_t)(b1 * NHEAD + h) * DHEAD + dh) * SEQ;
                Ct[base0 + s0] = __float2half_rn(v00);
                Ct[base0 + SEQ + s0] = __float2half_rn(v01);
                Ct[base1 + s1] = __float2half_rn(v10);
                Ct[base1 + SEQ + s1] = __float2half_rn(v11);
            }
        }
    }
}

// ============================================================
// FP16 tensor-core flash attention: BQ=128 (8 warps), BKV=64,
// double-buffered cp.async. K [64][128] natural; V^T [128][64] pre-transposed.
// ============================================================
#define FKH 136                      // K tile stride (halfs)
#define FVH 72                       // V^T tile stride (halfs)
#define FPH 72                       // P tile stride (halfs)
#define KVH (64 * FKH + 128 * FVH)   // halfs per stage

__global__ void __launch_bounds__(256) flash_attn_f16_kernel(
    const __half* __restrict__ Q, const __half* __restrict__ K,
    const __half* __restrict__ Vt, float* __restrict__ O)
{
    __half* S0 = (__half*)g_smem;
    __half* S1 = S0 + KVH;
    __half* Ps = S1 + KVH;            // [128][72]

    const int tid = threadIdx.x;
    const int w = tid >> 5;           // 0..7
    const int lane = tid & 31;
    const int g = lane >> 2;
    const int t = lane & 3;
    const int q0 = blockIdx.x * 128;
    const int h  = blockIdx.y;
    const int b  = blockIdx.z;
    const float scale = 0.088388347648318447f;   // 1/sqrt(128)
    const size_t base = (size_t)b * SEQ * DMODEL + (size_t)h * DHEAD;
    const size_t vbase = (size_t)(b * NHEAD + h) * DHEAD * SEQ;

    const uint32_t s0_u = (uint32_t)__cvta_generic_to_shared(S0);
    const uint32_t s1_u = (uint32_t)__cvta_generic_to_shared(S1);

    auto stage_kv = [&](uint32_t su, int t0) {
        // K tile: 64 rows x 128 halfs (256B) = 1024 16B chunks
        #pragma unroll
        for (int i = 0; i < 4; i++) {
            int c = tid + i * 256;
            int r = c >> 4, o = c & 15;
            cp_async16(su + (uint32_t)(r * FKH + o * 8) * 2,
                       K + base + (size_t)(t0 + r) * DMODEL + o * 8);
        }
        // V^T tile: 128 rows (dh) x 64 halfs (128B) = 1024 chunks
        #pragma unroll
        for (int i = 0; i < 4; i++) {
            int c = tid + i * 256;
            int r = c >> 3, o = c & 7;
            cp_async16(su + (uint32_t)(64 * FKH + r * FVH + o * 8) * 2,
                       Vt + vbase + (size_t)r * SEQ + t0 + o * 8);
        }
        cp_commit();
    };

    // Q fragments: warp w owns rows q0+16w+g, +8; 8 k-steps of 16
    uint32_t qa[8][4];
    {
        const __half* Qp0 = Q + base + (size_t)(q0 + w * 16 + g) * DMODEL;
        const __half* Qp1 = Qp0 + (size_t)8 * DMODEL;
        #pragma unroll
        for (int kk = 0; kk < 8; kk++) {
            qa[kk][0] = *(const uint32_t*)&Qp0[kk * 16 + 2 * t];
            qa[kk][1] = *(const uint32_t*)&Qp1[kk * 16 + 2 * t];
            qa[kk][2] = *(const uint32_t*)&Qp0[kk * 16 + 2 * t + 8];
            qa[kk][3] = *(const uint32_t*)&Qp1[kk * 16 + 2 * t + 8];
        }
    }

    float o_acc[16][4];
    #pragma unroll
    for (int ni = 0; ni < 16; ni++)
        #pragma unroll
        for (int r = 0; r < 4; r++) o_acc[ni][r] = 0.f;
    float m0r = -1e30f, m1r = -1e30f, l0r = 0.f, l1r = 0.f;

    stage_kv(s0_u, 0);
    asm volatile("cp.async.wait_group 0;\n");
    __syncthreads();

    for (int it = 0; it < SEQ / 64; it++) {
        const __half* Ks = (it & 1) ? S1 : S0;
        const __half* Vs = Ks + 64 * FKH;
        if (it + 1 < SEQ / 64) {
            stage_kv((it & 1) ? s0_u : s1_u, (it + 1) * 64);
        }

        // S = Q K^T  (8 k-steps x 8 n-tiles)
        float s[8][4];
        #pragma unroll
        for (int ni = 0; ni < 8; ni++)
            #pragma unroll
            for (int r = 0; r < 4; r++) s[ni][r] = 0.f;

        #pragma unroll
        for (int kk = 0; kk < 8; kk++) {
            #pragma unroll
            for (int ni = 0; ni < 8; ni++) {
                uint32_t bfr[2];
                const __half* kr = Ks + (ni * 8 + g) * FKH + kk * 16 + 2 * t;
                bfr[0] = *(const uint32_t*)kr;
                bfr[1] = *(const uint32_t*)(kr + 8);
                mma_f16(s[ni], qa[kk], bfr);
            }
        }

        // scale + online softmax
        #pragma unroll
        for (int ni = 0; ni < 8; ni++) {
            s[ni][0] *= scale; s[ni][1] *= scale;
            s[ni][2] *= scale; s[ni][3] *= scale;
        }
        float mt0 = -1e30f, mt1 = -1e30f;
        #pragma unroll
        for (int ni = 0; ni < 8; ni++) {
            mt0 = fmaxf(mt0, fmaxf(s[ni][0], s[ni][1]));
            mt1 = fmaxf(mt1, fmaxf(s[ni][2], s[ni][3]));
        }
        #pragma unroll
        for (int off = 1; off <= 2; off <<= 1) {
            mt0 = fmaxf(mt0, __shfl_xor_sync(0xffffffffu, mt0, off));
            mt1 = fmaxf(mt1, __shfl_xor_sync(0xffffffffu, mt1, off));
        }
        float mn0 = fmaxf(m0r, mt0), mn1 = fmaxf(m1r, mt1);
        float c0 = __expf(m0r - mn0), c1 = __expf(m1r - mn1);
        float rs0 = 0.f, rs1 = 0.f;
        #pragma unroll
        for (int ni = 0; ni < 8; ni++) {
            s[ni][0] = __expf(s[ni][0] - mn0);
            s[ni][1] = __expf(s[ni][1] - mn0);
            s[ni][2] = __expf(s[ni][2] - mn1);
            s[ni][3] = __expf(s[ni][3] - mn1);
            rs0 += s[ni][0] + s[ni][1];
            rs1 += s[ni][2] + s[ni][3];
        }
        #pragma unroll
        for (int off = 1; off <= 2; off <<= 1) {
            rs0 += __shfl_xor_sync(0xffffffffu, rs0, off);
            rs1 += __shfl_xor_sync(0xffffffffu, rs1, off);
        }
        l0r = l0r * c0 + rs0;  m0r = mn0;
        l1r = l1r * c1 + rs1;  m1r = mn1;
        #pragma unroll
        for (int ni = 0; ni < 16; ni++) {
            o_acc[ni][0] *= c0; o_acc[ni][1] *= c0;
            o_acc[ni][2] *= c1; o_acc[ni][3] *= c1;
        }

        // stage P (half2) into per-warp region
        {
            __half* p0 = Ps + (w * 16 + g) * FPH;
            __half* p1 = Ps + (w * 16 + 8 + g) * FPH;
            #pragma unroll
            for (int ni = 0; ni < 8; ni++) {
                *(uint32_t*)&p0[ni * 8 + 2 * t] = pack_h2(s[ni][0], s[ni][1]);
                *(uint32_t*)&p1[ni * 8 + 2 * t] = pack_h2(s[ni][2], s[ni][3]);
            }
        }
        __syncwarp();

        // O += P @ V  (4 k-steps of 16 over kv, 16 n-tiles over dh)
        #pragma unroll
        for (int kk = 0; kk < 4; kk++) {
            uint32_t pa[4];
            const __half* pr0 = Ps + (w * 16 + g) * FPH + kk * 16 + 2 * t;
            const __half* pr1 = Ps + (w * 16 + 8 + g) * FPH + kk * 16 + 2 * t;
            pa[0] = *(const uint32_t*)pr0;
            pa[1] = *(const uint32_t*)pr1;
            pa[2] = *(const uint32_t*)(pr0 + 8);
            pa[3] = *(const uint32_t*)(pr1 + 8);
            #pragma unroll
            for (int ni = 0; ni < 16; ni++) {
                uint32_t vb[2];
                const __half* vr = Vs + (ni * 8 + g) * FVH + kk * 16 + 2 * t;
                vb[0] = *(const uint32_t*)vr;
                vb[1] = *(const uint32_t*)(vr + 8);
                mma_f16(o_acc[ni], pa, vb);
            }
        }

        asm volatile("cp.async.wait_group 0;\n");
        __syncthreads();
    }

    float inv0 = 1.f / l0r, inv1 = 1.f / l1r;
    size_t ob0 = (((size_t)b * NHEAD + h) * SEQ + (q0 + w * 16 + g)) * DHEAD;
    size_t ob1 = ob0 + (size_t)8 * DHEAD;
    #pragma unroll
    for (int ni = 0; ni < 16; ni++) {
        int cb = ni * 8 + 2 * t;
        *(float2*)(O + ob0 + cb) = make_float2(o_acc[ni][0] * inv0, o_acc[ni][1] * inv0);
        *(float2*)(O + ob1 + cb) = make_float2(o_acc[ni][2] * inv1, o_acc[ni][3] * inv1);
    }
}

// ============================================================
// out = LayerNorm(A + Bb) * gamma + beta   (row = 2048)
// ============================================================
template <bool OUT_HALF>
__global__ void __launch_bounds__(256) add_ln_kernel(
    const float* __restrict__ A, const float* __restrict__ Bb,
    const float* __restrict__ gamma, const float* __restrict__ beta,
    void* __restrict__ outv)
{
    const int row = blockIdx.x;
    const int tid = threadIdx.x;
    const float* a  = A  + (size_t)row * DMODEL;
    const float* bb = Bb + (size_t)row * DMODEL;

    float v[8];
    float s = 0.f, sq = 0.f;
    #pragma unroll
    for (int i = 0; i < 8; i++) {
        int idx = tid + i * 256;
        float x = a[idx] + bb[idx];
        v[i] = x;
        s += x;
        sq += x * x;
    }
    #pragma unroll
    for (int off = 16; off >= 1; off >>= 1) {
        s  += __shfl_xor_sync(0xffffffffu, s, off);
        sq += __shfl_xor_sync(0xffffffffu, sq, off);
    }
    __shared__ float red[2][8];
    __shared__ float fmean, finv;
    int wid = tid >> 5, lane = tid & 31;
    if (lane == 0) { red[0][wid] = s; red[1][wid] = sq; }
    __syncthreads();
    if (tid == 0) {
        float ts = 0.f, tq = 0.f;
        #pragma unroll
        for (int w = 0; w < 8; w++) { ts += red[0][w]; tq += red[1][w]; }
        float mean = ts * (1.f / DMODEL);
        float var = tq * (1.f / DMODEL) - mean * mean;
        fmean = mean;
        finv = rsqrtf(var + 1e-5f);
    }
    __syncthreads();
    float mean = fmean, inv = finv;
    #pragma unroll
    for (int i = 0; i < 8; i++) {
        int idx = tid + i * 256;
        float r = (v[i] - mean) * inv * gamma[idx] + beta[idx];
        if (OUT_HALF) {
            ((__half*)outv)[(size_t)row * DMODEL + idx] = __float2half_rn(r);
        } else {
            ((float*)outv)[(size_t)row * DMODEL + idx] = r;
        }
    }
}

// ============================================================
extern "C" void kernel_launch(void* const* d_in, const int* in_sizes, int n_in,
                              void* d_out, int out_size)
{
    const float* x     = (const float*)d_in[0];
    const float* wq    = (const float*)d_in[1];
    const float* bq    = (const float*)d_in[2];
    const float* wk    = (const float*)d_in[3];
    const float* bk    = (const float*)d_in[4];
    const float* wv    = (const float*)d_in[5];
    const float* bv    = (const float*)d_in[6];
    const float* wf    = (const float*)d_in[7];
    const float* bf    = (const float*)d_in[8];
    const float* gamma = (const float*)d_in[9];
    const float* beta  = (const float*)d_in[10];
    float* out = (float*)d_out;

    __half *xh, *wqt, *wkt, *wvt, *wft, *q, *k, *vt, *h1;
    float *o, *h2;
    cudaGetSymbolAddress((void**)&xh,  g_xh);
    cudaGetSymbolAddress((void**)&wqt, g_wqt);
    cudaGetSymbolAddress((void**)&wkt, g_wkt);
    cudaGetSymbolAddress((void**)&wvt, g_wvt);
    cudaGetSymbolAddress((void**)&wft, g_wft);
    cudaGetSymbolAddress((void**)&q,   g_q);
    cudaGetSymbolAddress((void**)&k,   g_k);
    cudaGetSymbolAddress((void**)&vt,  g_vt);
    cudaGetSymbolAddress((void**)&h1,  g_h1);
    cudaGetSymbolAddress((void**)&o,   g_o);
    cudaGetSymbolAddress((void**)&h2,  g_h2);

    const dim3 gemm_grid(DMODEL / TBN, MTOK / TBM);              // (16, 32)
    const size_t gemm_smem = 2 * HSTAGE * sizeof(__half);        // 40960
    const size_t fa_bytes = (size_t)(2 * KVH + 128 * FPH) * sizeof(__half); // ~90KB
    const dim3 tgrid(DMODEL / 32, DMODEL / 32);

    static int attr_done = 0;
    if (!attr_done) {
        cudaFuncSetAttribute(gemm_f16_kernel,
                             cudaFuncAttributeMaxDynamicSharedMemorySize,
                             (int)gemm_smem);
        cudaFuncSetAttribute(flash_attn_f16_kernel,
                             cudaFuncAttributeMaxDynamicSharedMemorySize,
                             (int)fa_bytes);
        attr_done = 1;
    }

    // pre-pass: x -> half; weights -> transposed half
    cvt_half_kernel<<<MTOK * DMODEL / 2048, 256>>>(x, xh);
    cvt_transpose_kernel<<<tgrid, 256>>>(wq, wqt);
    cvt_transpose_kernel<<<tgrid, 256>>>(wk, wkt);
    cvt_transpose_kernel<<<tgrid, 256>>>(wv, wvt);
    cvt_transpose_kernel<<<tgrid, 256>>>(wf, wft);

    gemm_f16_kernel<<<gemm_grid, 256, gemm_smem>>>(xh, wqt, bq, q, 1);
    gemm_f16_kernel<<<gemm_grid, 256, gemm_smem>>>(xh, wkt, bk, k, 1);
    gemm_f16_kernel<<<gemm_grid, 256, gemm_smem>>>(xh, wvt, bv, vt, 2);

    flash_attn_f16_kernel<<<dim3(SEQ / 128, NHEAD, BATCH), 256, fa_bytes>>>(q, k, vt, o);

    add_ln_kernel<true><<<MTOK, 256>>>(o, x, gamma, beta, h1);
    gemm_f16_kernel<<<gemm_grid, 256, gemm_smem>>>(h1, wft, bf, h2, 0);
    add_ln_kernel<false><<<MTOK, 256>>>(h2, o, gamma, beta, out);
}

// round 9
// speedup vs baseline: 8.9576x; 1.1793x over previous
#include <cuda_runtime.h>
#include <cuda_fp16.h>
#include <cstdint>

#define MTOK 4096      // B*S
#define DMODEL 2048
#define NHEAD 16
#define DHEAD 128
#define BATCH 2
#define SEQ 2048

// ---- scratch (no cudaMalloc allowed) ----
__device__ __half  g_xh[MTOK * DMODEL];        // half(x) [M][K]
__device__ __half  g_wqt[DMODEL * DMODEL];     // W^T [N][K] half
__device__ __half  g_wkt[DMODEL * DMODEL];
__device__ __half  g_wvt[DMODEL * DMODEL];
__device__ __half  g_wft[DMODEL * DMODEL];
__device__ __half  g_q[MTOK * DMODEL];         // [M][N] half
__device__ __half  g_k[MTOK * DMODEL];         // [M][N] half
__device__ __half  g_vt[MTOK * DMODEL];        // V^T per head: [b][h][dh][s]
__device__ __half  g_h1[MTOK * DMODEL];        // half (feeds FF gemm)
__device__ float   g_o[MTOK * DMODEL];         // [B,H,S,DH] contig == buggy flat view
__device__ float   g_h2[MTOK * DMODEL];

extern __shared__ float g_smem[];

// ============================================================
// helpers
// ============================================================
__device__ __forceinline__ void cp_async16(uint32_t saddr, const void* gaddr) {
    asm volatile("cp.async.cg.shared.global [%0], [%1], 16;\n" :: "r"(saddr), "l"(gaddr));
}
__device__ __forceinline__ void cp_commit() {
    asm volatile("cp.async.commit_group;\n");
}
__device__ __forceinline__ uint32_t pack_h2(float a, float b) {
    __half2 h = __floats2half2_rn(a, b);
    return *(uint32_t*)&h;
}
__device__ __forceinline__ void mma_f16(float* c, const uint32_t* a, const uint32_t* b) {
    asm volatile(
        "mma.sync.aligned.m16n8k16.row.col.f32.f16.f16.f32 "
        "{%0,%1,%2,%3}, {%4,%5,%6,%7}, {%8,%9}, {%0,%1,%2,%3};\n"
        : "+f"(c[0]), "+f"(c[1]), "+f"(c[2]), "+f"(c[3])
        : "r"(a[0]), "r"(a[1]), "r"(a[2]), "r"(a[3]), "r"(b[0]), "r"(b[1]));
}
__device__ __forceinline__ void ldsm_x4(uint32_t& r0, uint32_t& r1, uint32_t& r2, uint32_t& r3,
                                        uint32_t addr) {
    asm volatile("ldmatrix.sync.aligned.m8n8.x4.shared.b16 {%0,%1,%2,%3}, [%4];"
                 : "=r"(r0), "=r"(r1), "=r"(r2), "=r"(r3) : "r"(addr));
}

// ============================================================
// pre-pass: x -> half (same layout)
// ============================================================
__global__ void __launch_bounds__(256) cvt_half_kernel(
    const float* __restrict__ in, __half* __restrict__ out)
{
    int i = (blockIdx.x * 256 + threadIdx.x) * 8;
    float4 v0 = *(const float4*)(in + i);
    float4 v1 = *(const float4*)(in + i + 4);
    uint4 o;
    o.x = pack_h2(v0.x, v0.y);
    o.y = pack_h2(v0.z, v0.w);
    o.z = pack_h2(v1.x, v1.y);
    o.w = pack_h2(v1.z, v1.w);
    *(uint4*)((__half*)out + i) = o;
}

// pre-pass: W [K][N] fp32 -> W^T [N][K] half (smem transpose)
__global__ void __launch_bounds__(256) cvt_transpose_kernel(
    const float* __restrict__ in, __half* __restrict__ out)
{
    __shared__ __half tile[32][33];
    const int n0 = blockIdx.x * 32;
    const int k0 = blockIdx.y * 32;
    const int tx = threadIdx.x & 31;
    const int ty = threadIdx.x >> 5;   // 0..7
    #pragma unroll
    for (int i = 0; i < 32; i += 8)
        tile[ty + i][tx] = __float2half_rn(in[(size_t)(k0 + ty + i) * DMODEL + n0 + tx]);
    __syncthreads();
    #pragma unroll
    for (int i = 0; i < 32; i += 8)
        out[(size_t)(n0 + ty + i) * DMODEL + k0 + tx] = tile[tx][ty + i];
}

// ============================================================
// FP16 tensor-core GEMM: C[M,N] = A[M,K](half) @ Wt[N,K](half)^T + bias
// block 128x128x32, 8 warps (64x32 warp tiles), 2-stage cp.async, ldmatrix frags
// out_mode: 0 = fp32 [M][N], 1 = half [M][N], 2 = half V^T per-head
// ============================================================
#define TBM 128
#define TBN 128
#define TBK 32
#define HS 40                         // smem row stride in halfs (80B; ldmatrix conflict-free)
#define HTILE (128 * HS)              // halfs per tile
#define HSTAGE (2 * HTILE)            // A+B halfs per stage

__global__ void __launch_bounds__(256, 2) gemm_f16_kernel(
    const __half* __restrict__ A, const __half* __restrict__ Wt,
    const float* __restrict__ bias, void* __restrict__ Cout,
    int out_mode)
{
    const int tid = threadIdx.x;
    const int wid = tid >> 5;
    const int lane = tid & 31;
    const int g = lane >> 2;
    const int t = lane & 3;
    const int wr = wid >> 2;
    const int wc = wid & 3;
    const int R = wr * 64;
    const int Cc = wc * 32;
    const int rowBase = blockIdx.y * TBM;
    const int colBase = blockIdx.x * TBN;
    const int K = DMODEL, N = DMODEL;

    // ldmatrix lane->address components
    const int a_row = lane & 15;                 // row within m16 tile
    const int a_c8  = (lane >> 4) << 3;          // +8 cols for lanes 16-31
    const int b_row = ((lane >> 4) << 3) | (lane & 7);  // row within n16 pair
    const int b_c8  = ((lane >> 3) & 1) << 3;    // +8 cols for lanes 8-15, 24-31

    __half* stage[2] = { (__half*)g_smem, (__half*)g_smem + HSTAGE };

    auto load_stage = [&](int s, int k0) {
        __half* as = stage[s];
        __half* bs = stage[s] + HTILE;
        uint32_t as_u = (uint32_t)__cvta_generic_to_shared(as);
        uint32_t bs_u = (uint32_t)__cvta_generic_to_shared(bs);
        #pragma unroll
        for (int i = 0; i < 2; i++) {
            int c = tid + i * 256;          // 0..511
            int r = c >> 2;                 // 0..127
            int o = c & 3;                  // 16B chunk (8 halfs)
            cp_async16(as_u + (uint32_t)(r * HS + o * 8) * 2,
                       A + (size_t)(rowBase + r) * K + k0 + o * 8);
        }
        #pragma unroll
        for (int i = 0; i < 2; i++) {
            int c = tid + i * 256;
            int n = c >> 2;
            int o = c & 3;
            cp_async16(bs_u + (uint32_t)(n * HS + o * 8) * 2,
                       Wt + (size_t)(colBase + n) * K + k0 + o * 8);
        }
        cp_commit();
    };

    float acc[4][4][4];
    #pragma unroll
    for (int mi = 0; mi < 4; mi++)
        #pragma unroll
        for (int ni = 0; ni < 4; ni++)
            #pragma unroll
            for (int r = 0; r < 4; r++) acc[mi][ni][r] = 0.f;

    const int T = K / TBK;   // 64
    load_stage(0, 0);

    int buf = 0;
    for (int it = 0; it < T; it++) {
        if (it + 1 < T) {
            load_stage(buf ^ 1, (it + 1) * TBK);
            asm volatile("cp.async.wait_group 1;\n");
        } else {
            asm volatile("cp.async.wait_group 0;\n");
        }
        __syncthreads();

        uint32_t as_u = (uint32_t)__cvta_generic_to_shared(stage[buf]);
        uint32_t bs_u = (uint32_t)__cvta_generic_to_shared(stage[buf] + HTILE);

        #pragma unroll
        for (int ks = 0; ks < 2; ks++) {
            const int kk = ks * 16;
            uint32_t af[4][4], bf[4][2];
            #pragma unroll
            for (int mi = 0; mi < 4; mi++) {
                uint32_t addr = as_u + 2u * (uint32_t)((R + mi * 16 + a_row) * HS + kk + a_c8);
                ldsm_x4(af[mi][0], af[mi][1], af[mi][2], af[mi][3], addr);
            }
            #pragma unroll
            for (int pr = 0; pr < 2; pr++) {
                uint32_t addr = bs_u + 2u * (uint32_t)((Cc + pr * 16 + b_row) * HS + kk + b_c8);
                ldsm_x4(bf[2 * pr][0], bf[2 * pr][1], bf[2 * pr + 1][0], bf[2 * pr + 1][1], addr);
            }
            #pragma unroll
            for (int mi = 0; mi < 4; mi++)
                #pragma unroll
                for (int ni = 0; ni < 4; ni++)
                    mma_f16(acc[mi][ni], af[mi], bf[ni]);
        }
        __syncthreads();
        buf ^= 1;
    }

    #pragma unroll
    for (int mi = 0; mi < 4; mi++) {
        int r0 = rowBase + R + mi * 16 + g;
        #pragma unroll
        for (int ni = 0; ni < 4; ni++) {
            int cb = colBase + Cc + ni * 8 + 2 * t;
            float bx = bias[cb], by = bias[cb + 1];
            float v00 = acc[mi][ni][0] + bx, v01 = acc[mi][ni][1] + by;
            float v10 = acc[mi][ni][2] + bx, v11 = acc[mi][ni][3] + by;
            if (out_mode == 0) {
                float* Cf = (float*)Cout;
                *(float2*)(Cf + (size_t)r0 * N + cb) = make_float2(v00, v01);
                *(float2*)(Cf + (size_t)(r0 + 8) * N + cb) = make_float2(v10, v11);
            } else if (out_mode == 1) {
                __half* Ch = (__half*)Cout;
                *(uint32_t*)(Ch + (size_t)r0 * N + cb) = pack_h2(v00, v01);
                *(uint32_t*)(Ch + (size_t)(r0 + 8) * N + cb) = pack_h2(v10, v11);
            } else {
                // V^T per head: (m, n) -> [b][h][dh][s]; b=m>>11, s=m&2047
                __half* Ct = (__half*)Cout;
                int b0 = r0 >> 11, s0 = r0 & 2047;
                int b1 = (r0 + 8) >> 11, s1 = (r0 + 8) & 2047;
                int h = cb >> 7, dh = cb & 127;
                size_t base0 = ((size_t)(b0 * NHEAD + h) * DHEAD + dh) * SEQ;
                size_t base1 = ((size_t)(b1 * NHEAD + h) * DHEAD + dh) * SEQ;
                Ct[base0 + s0] = __float2half_rn(v00);
                Ct[base0 + SEQ + s0] = __float2half_rn(v01);
                Ct[base1 + s1] = __float2half_rn(v10);
                Ct[base1 + SEQ + s1] = __float2half_rn(v11);
            }
        }
    }
}

// ============================================================
// FP16 tensor-core flash attention: BQ=128 (8 warps), BKV=64,
// double-buffered cp.async, ldmatrix frags. V^T pre-transposed.
// ============================================================
#define FKH 136                      // K tile stride (halfs; ldmatrix conflict-free)
#define FVH 72                       // V^T tile stride (halfs)
#define FPH 72                       // P tile stride (halfs)
#define KVH (64 * FKH + 128 * FVH)   // halfs per stage

__global__ void __launch_bounds__(256) flash_attn_f16_kernel(
    const __half* __restrict__ Q, const __half* __restrict__ K,
    const __half* __restrict__ Vt, float* __restrict__ O)
{
    __half* S0 = (__half*)g_smem;
    __half* S1 = S0 + KVH;
    __half* Ps = S1 + KVH;            // [128][72]

    const int tid = threadIdx.x;
    const int w = tid >> 5;           // 0..7
    const int lane = tid & 31;
    const int g = lane >> 2;
    const int t = lane & 3;
    const int q0 = blockIdx.x * 128;
    const int h  = blockIdx.y;
    const int b  = blockIdx.z;
    const float scale = 0.088388347648318447f;   // 1/sqrt(128)
    const size_t base = (size_t)b * SEQ * DMODEL + (size_t)h * DHEAD;
    const size_t vbase = (size_t)(b * NHEAD + h) * DHEAD * SEQ;

    const int a_row = lane & 15;
    const int a_c8  = (lane >> 4) << 3;
    const int b_row = ((lane >> 4) << 3) | (lane & 7);
    const int b_c8  = ((lane >> 3) & 1) << 3;

    const uint32_t s0_u = (uint32_t)__cvta_generic_to_shared(S0);
    const uint32_t s1_u = (uint32_t)__cvta_generic_to_shared(S1);
    const uint32_t ps_u = (uint32_t)__cvta_generic_to_shared(Ps);

    auto stage_kv = [&](uint32_t su, int t0) {
        #pragma unroll
        for (int i = 0; i < 4; i++) {
            int c = tid + i * 256;
            int r = c >> 4, o = c & 15;
            cp_async16(su + (uint32_t)(r * FKH + o * 8) * 2,
                       K + base + (size_t)(t0 + r) * DMODEL + o * 8);
        }
        #pragma unroll
        for (int i = 0; i < 4; i++) {
            int c = tid + i * 256;
            int r = c >> 3, o = c & 7;
            cp_async16(su + (uint32_t)(64 * FKH + r * FVH + o * 8) * 2,
                       Vt + vbase + (size_t)r * SEQ + t0 + o * 8);
        }
        cp_commit();
    };

    // Q fragments from global (once)
    uint32_t qa[8][4];
    {
        const __half* Qp0 = Q + base + (size_t)(q0 + w * 16 + g) * DMODEL;
        const __half* Qp1 = Qp0 + (size_t)8 * DMODEL;
        #pragma unroll
        for (int kk = 0; kk < 8; kk++) {
            qa[kk][0] = *(const uint32_t*)&Qp0[kk * 16 + 2 * t];
            qa[kk][1] = *(const uint32_t*)&Qp1[kk * 16 + 2 * t];
            qa[kk][2] = *(const uint32_t*)&Qp0[kk * 16 + 2 * t + 8];
            qa[kk][3] = *(const uint32_t*)&Qp1[kk * 16 + 2 * t + 8];
        }
    }

    float o_acc[16][4];
    #pragma unroll
    for (int ni = 0; ni < 16; ni++)
        #pragma unroll
        for (int r = 0; r < 4; r++) o_acc[ni][r] = 0.f;
    float m0r = -1e30f, m1r = -1e30f, l0r = 0.f, l1r = 0.f;

    stage_kv(s0_u, 0);
    asm volatile("cp.async.wait_group 0;\n");
    __syncthreads();

    for (int it = 0; it < SEQ / 64; it++) {
        const uint32_t ks_u = (it & 1) ? s1_u : s0_u;
        const uint32_t vs_u = ks_u + 64 * FKH * 2;
        if (it + 1 < SEQ / 64) {
            stage_kv((it & 1) ? s0_u : s1_u, (it + 1) * 64);
        }

        // S = Q K^T  (8 k-steps x 8 n-tiles; K frags via ldmatrix pairs)
        float s[8][4];
        #pragma unroll
        for (int ni = 0; ni < 8; ni++)
            #pragma unroll
            for (int r = 0; r < 4; r++) s[ni][r] = 0.f;

        #pragma unroll
        for (int kk = 0; kk < 8; kk++) {
            uint32_t kf[8][2];
            #pragma unroll
            for (int pr = 0; pr < 4; pr++) {
                uint32_t addr = ks_u + 2u * (uint32_t)((pr * 16 + b_row) * FKH + kk * 16 + b_c8);
                ldsm_x4(kf[2 * pr][0], kf[2 * pr][1], kf[2 * pr + 1][0], kf[2 * pr + 1][1], addr);
            }
            #pragma unroll
            for (int ni = 0; ni < 8; ni++)
                mma_f16(s[ni], qa[kk], kf[ni]);
        }

        // scale + online softmax
        #pragma unroll
        for (int ni = 0; ni < 8; ni++) {
            s[ni][0] *= scale; s[ni][1] *= scale;
            s[ni][2] *= scale; s[ni][3] *= scale;
        }
        float mt0 = -1e30f, mt1 = -1e30f;
        #pragma unroll
        for (int ni = 0; ni < 8; ni++) {
            mt0 = fmaxf(mt0, fmaxf(s[ni][0], s[ni][1]));
            mt1 = fmaxf(mt1, fmaxf(s[ni][2], s[ni][3]));
        }
        #pragma unroll
        for (int off = 1; off <= 2; off <<= 1) {
            mt0 = fmaxf(mt0, __shfl_xor_sync(0xffffffffu, mt0, off));
            mt1 = fmaxf(mt1, __shfl_xor_sync(0xffffffffu, mt1, off));
        }
        float mn0 = fmaxf(m0r, mt0), mn1 = fmaxf(m1r, mt1);
        float c0 = __expf(m0r - mn0), c1 = __expf(m1r - mn1);
        float rs0 = 0.f, rs1 = 0.f;
        #pragma unroll
        for (int ni = 0; ni < 8; ni++) {
            s[ni][0] = __expf(s[ni][0] - mn0);
            s[ni][1] = __expf(s[ni][1] - mn0);
            s[ni][2] = __expf(s[ni][2] - mn1);
            s[ni][3] = __expf(s[ni][3] - mn1);
            rs0 += s[ni][0] + s[ni][1];
            rs1 += s[ni][2] + s[ni][3];
        }
        #pragma unroll
        for (int off = 1; off <= 2; off <<= 1) {
            rs0 += __shfl_xor_sync(0xffffffffu, rs0, off);
            rs1 += __shfl_xor_sync(0xffffffffu, rs1, off);
        }
        l0r = l0r * c0 + rs0;  m0r = mn0;
        l1r = l1r * c1 + rs1;  m1r = mn1;
        #pragma unroll
        for (int ni = 0; ni < 16; ni++) {
            o_acc[ni][0] *= c0; o_acc[ni][1] *= c0;
            o_acc[ni][2] *= c1; o_acc[ni][3] *= c1;
        }

        // stage P (half2) into per-warp region
        {
            __half* p0 = Ps + (w * 16 + g) * FPH;
            __half* p1 = Ps + (w * 16 + 8 + g) * FPH;
            #pragma unroll
            for (int ni = 0; ni < 8; ni++) {
                *(uint32_t*)&p0[ni * 8 + 2 * t] = pack_h2(s[ni][0], s[ni][1]);
                *(uint32_t*)&p1[ni * 8 + 2 * t] = pack_h2(s[ni][2], s[ni][3]);
            }
        }
        __syncwarp();

        // O += P @ V  (4 k-steps of 16; P via ldmatrix A-pattern, V via pairs)
        #pragma unroll
        for (int kk = 0; kk < 4; kk++) {
            uint32_t pa[4];
            {
                uint32_t addr = ps_u + 2u * (uint32_t)((w * 16 + a_row) * FPH + kk * 16 + a_c8);
                ldsm_x4(pa[0], pa[1], pa[2], pa[3], addr);
            }
            uint32_t vf[16][2];
            #pragma unroll
            for (int pr = 0; pr < 8; pr++) {
                uint32_t addr = vs_u + 2u * (uint32_t)((pr * 16 + b_row) * FVH + kk * 16 + b_c8);
                ldsm_x4(vf[2 * pr][0], vf[2 * pr][1], vf[2 * pr + 1][0], vf[2 * pr + 1][1], addr);
            }
            #pragma unroll
            for (int ni = 0; ni < 16; ni++)
                mma_f16(o_acc[ni], pa, vf[ni]);
        }

        asm volatile("cp.async.wait_group 0;\n");
        __syncthreads();
    }

    float inv0 = 1.f / l0r, inv1 = 1.f / l1r;
    size_t ob0 = (((size_t)b * NHEAD + h) * SEQ + (q0 + w * 16 + g)) * DHEAD;
    size_t ob1 = ob0 + (size_t)8 * DHEAD;
    #pragma unroll
    for (int ni = 0; ni < 16; ni++) {
        int cb = ni * 8 + 2 * t;
        *(float2*)(O + ob0 + cb) = make_float2(o_acc[ni][0] * inv0, o_acc[ni][1] * inv0);
        *(float2*)(O + ob1 + cb) = make_float2(o_acc[ni][2] * inv1, o_acc[ni][3] * inv1);
    }
}

// ============================================================
// out = LayerNorm(A + Bb) * gamma + beta   (row = 2048)
// ============================================================
template <bool OUT_HALF>
__global__ void __launch_bounds__(256) add_ln_kernel(
    const float* __restrict__ A, const float* __restrict__ Bb,
    const float* __restrict__ gamma, const float* __restrict__ beta,
    void* __restrict__ outv)
{
    const int row = blockIdx.x;
    const int tid = threadIdx.x;
    const float* a  = A  + (size_t)row * DMODEL;
    const float* bb = Bb + (size_t)row * DMODEL;

    float v[8];
    float s = 0.f, sq = 0.f;
    #pragma unroll
    for (int i = 0; i < 8; i++) {
        int idx = tid + i * 256;
        float x = a[idx] + bb[idx];
        v[i] = x;
        s += x;
        sq += x * x;
    }
    #pragma unroll
    for (int off = 16; off >= 1; off >>= 1) {
        s  += __shfl_xor_sync(0xffffffffu, s, off);
        sq += __shfl_xor_sync(0xffffffffu, sq, off);
    }
    __shared__ float red[2][8];
    __shared__ float fmean, finv;
    int wid = tid >> 5, lane = tid & 31;
    if (lane == 0) { red[0][wid] = s; red[1][wid] = sq; }
    __syncthreads();
    if (tid == 0) {
        float ts = 0.f, tq = 0.f;
        #pragma unroll
        for (int w = 0; w < 8; w++) { ts += red[0][w]; tq += red[1][w]; }
        float mean = ts * (1.f / DMODEL);
        float var = tq * (1.f / DMODEL) - mean * mean;
        fmean = mean;
        finv = rsqrtf(var + 1e-5f);
    }
    __syncthreads();
    float mean = fmean, inv = finv;
    #pragma unroll
    for (int i = 0; i < 8; i++) {
        int idx = tid + i * 256;
        float r = (v[i] - mean) * inv * gamma[idx] + beta[idx];
        if (OUT_HALF) {
            ((__half*)outv)[(size_t)row * DMODEL + idx] = __float2half_rn(r);
        } else {
            ((float*)outv)[(size_t)row * DMODEL + idx] = r;
        }
    }
}

// ============================================================
extern "C" void kernel_launch(void* const* d_in, const int* in_sizes, int n_in,
                              void* d_out, int out_size)
{
    const float* x     = (const float*)d_in[0];
    const float* wq    = (const float*)d_in[1];
    const float* bq    = (const float*)d_in[2];
    const float* wk    = (const float*)d_in[3];
    const float* bk    = (const float*)d_in[4];
    const float* wv    = (const float*)d_in[5];
    const float* bv    = (const float*)d_in[6];
    const float* wf    = (const float*)d_in[7];
    const float* bf    = (const float*)d_in[8];
    const float* gamma = (const float*)d_in[9];
    const float* beta  = (const float*)d_in[10];
    float* out = (float*)d_out;

    __half *xh, *wqt, *wkt, *wvt, *wft, *q, *k, *vt, *h1;
    float *o, *h2;
    cudaGetSymbolAddress((void**)&xh,  g_xh);
    cudaGetSymbolAddress((void**)&wqt, g_wqt);
    cudaGetSymbolAddress((void**)&wkt, g_wkt);
    cudaGetSymbolAddress((void**)&wvt, g_wvt);
    cudaGetSymbolAddress((void**)&wft, g_wft);
    cudaGetSymbolAddress((void**)&q,   g_q);
    cudaGetSymbolAddress((void**)&k,   g_k);
    cudaGetSymbolAddress((void**)&vt,  g_vt);
    cudaGetSymbolAddress((void**)&h1,  g_h1);
    cudaGetSymbolAddress((void**)&o,   g_o);
    cudaGetSymbolAddress((void**)&h2,  g_h2);

    const dim3 gemm_grid(DMODEL / TBN, MTOK / TBM);              // (16, 32)
    const size_t gemm_smem = 2 * HSTAGE * sizeof(__half);        // 40960
    const size_t fa_bytes = (size_t)(2 * KVH + 128 * FPH) * sizeof(__half); // ~90KB
    const dim3 tgrid(DMODEL / 32, DMODEL / 32);

    static int attr_done = 0;
    if (!attr_done) {
        cudaFuncSetAttribute(gemm_f16_kernel,
                             cudaFuncAttributeMaxDynamicSharedMemorySize,
                             (int)gemm_smem);
        cudaFuncSetAttribute(flash_attn_f16_kernel,
                             cudaFuncAttributeMaxDynamicSharedMemorySize,
                             (int)fa_bytes);
        attr_done = 1;
    }

    // pre-pass: x -> half; weights -> transposed half
    cvt_half_kernel<<<MTOK * DMODEL / 2048, 256>>>(x, xh);
    cvt_transpose_kernel<<<tgrid, 256>>>(wq, wqt);
    cvt_transpose_kernel<<<tgrid, 256>>>(wk, wkt);
    cvt_transpose_kernel<<<tgrid, 256>>>(wv, wvt);
    cvt_transpose_kernel<<<tgrid, 256>>>(wf, wft);

    gemm_f16_kernel<<<gemm_grid, 256, gemm_smem>>>(xh, wqt, bq, q, 1);
    gemm_f16_kernel<<<gemm_grid, 256, gemm_smem>>>(xh, wkt, bk, k, 1);
    gemm_f16_kernel<<<gemm_grid, 256, gemm_smem>>>(xh, wvt, bv, vt, 2);

    flash_attn_f16_kernel<<<dim3(SEQ / 128, NHEAD, BATCH), 256, fa_bytes>>>(q, k, vt, o);

    add_ln_kernel<true><<<MTOK, 256>>>(o, x, gamma, beta, h1);
    gemm_f16_kernel<<<gemm_grid, 256, gemm_smem>>>(h1, wft, bf, h2, 0);
    add_ln_kernel<false><<<MTOK, 256>>>(h2, o, gamma, beta, out);
}